// round 1
// baseline (speedup 1.0000x reference)
#include <cuda_runtime.h>
#include <math.h>

// ---------------------------------------------------------------------------
// SelfAttention: B=4, N=4096, d_in=d_new=1024, fp32 in/out, rel_err < 1e-3.
// Strategy: tf32 tensor-core GEMMs (mma.sync.m16n8k8) + row softmax.
//   1) Q = X*Wq + bq ; K = X*Wk + bk ; V = X*Wv + bv      (M=16384,N=1024,K=1024)
//   2) S = Q * K^T * (1/32)   per batch                    (M=N=4096,K=1024)
//   3) P = softmax_rows(S)    in place
//   4) O = P * V              per batch                    (M=4096,N=1024,K=4096)
// Scratch via __device__ globals (no runtime allocation).
// ---------------------------------------------------------------------------

#define BM 128
#define BN 128
#define BK 32

// Scratch: Q,K,V = 4*4096*1024 floats each; S = 4*4096*4096 floats.
__device__ float g_Q[4 * 4096 * 1024];
__device__ float g_K[4 * 4096 * 1024];
__device__ float g_V[4 * 4096 * 1024];
__device__ float g_S[(size_t)4 * 4096 * 4096];

__device__ __forceinline__ unsigned f2tf(float x) {
    unsigned r;
    asm("cvt.rna.tf32.f32 %0, %1;" : "=r"(r) : "f"(x));
    return r;
}

__device__ __forceinline__ void mma_tf32(float c[4],
                                         unsigned a0, unsigned a1, unsigned a2, unsigned a3,
                                         unsigned b0, unsigned b1) {
    asm volatile(
        "mma.sync.aligned.m16n8k8.row.col.f32.tf32.tf32.f32 "
        "{%0,%1,%2,%3},{%4,%5,%6,%7},{%8,%9},{%0,%1,%2,%3};"
        : "+f"(c[0]), "+f"(c[1]), "+f"(c[2]), "+f"(c[3])
        : "r"(a0), "r"(a1), "r"(a2), "r"(a3), "r"(b0), "r"(b1));
}

// C[M,N] = alpha * A * op(B) + bias
//   A: [M,K] row-major.
//   TRANSB=false: B is [K,N] row-major.  TRANSB=true: B is [N,K] row-major (computes A*B^T).
// Batched over blockIdx.z via element strides sA, sB, sC. Dims must be multiples of tiles.
template <bool TRANSB>
__global__ void gemm_tf32(const float* __restrict__ A, const float* __restrict__ B,
                          const float* __restrict__ bias, float* __restrict__ C,
                          int M, int N, int K,
                          long long sA, long long sB, long long sC, float alpha) {
    A += (long long)blockIdx.z * sA;
    B += (long long)blockIdx.z * sB;
    C += (long long)blockIdx.z * sC;

    __shared__ unsigned As[BK][BM + 4];  // As[k][m]
    __shared__ unsigned Bs[BK][BN + 4];  // Bs[k][n]

    const int tid  = threadIdx.x;         // 256 threads
    const int lane = tid & 31;
    const int warp = tid >> 5;            // 8 warps: 2 (M) x 4 (N)
    const int wr   = warp & 1;            // warp row  -> 64 rows
    const int wc   = warp >> 1;           // warp col  -> 32 cols
    const int grp  = lane >> 2;
    const int tig  = lane & 3;

    const int m0 = blockIdx.y * BM;
    const int n0 = blockIdx.x * BN;

    float acc[4][4][4];
#pragma unroll
    for (int i = 0; i < 4; i++)
#pragma unroll
        for (int j = 0; j < 4; j++)
#pragma unroll
            for (int v = 0; v < 4; v++) acc[i][j][v] = 0.0f;

    for (int kt = 0; kt < K; kt += BK) {
        // ---- load A tile [BM x BK] -> As[k][m] (transposed, tf32-converted) ----
#pragma unroll
        for (int i = 0; i < 4; i++) {
            int linear = i * 256 + tid;           // 0..1023 (= 128 rows * 8 float4)
            int row = linear >> 3;
            int c4  = (linear & 7) << 2;
            const float4 v = *(const float4*)(A + (size_t)(m0 + row) * K + kt + c4);
            As[c4 + 0][row] = f2tf(v.x);
            As[c4 + 1][row] = f2tf(v.y);
            As[c4 + 2][row] = f2tf(v.z);
            As[c4 + 3][row] = f2tf(v.w);
        }
        // ---- load B tile -> Bs[k][n] ----
        if (TRANSB) {
            // B is [N,K] row-major: rows are n, cols are k. Same pattern as A.
#pragma unroll
            for (int i = 0; i < 4; i++) {
                int linear = i * 256 + tid;
                int row = linear >> 3;            // n within tile
                int c4  = (linear & 7) << 2;      // k within tile
                const float4 v = *(const float4*)(B + (size_t)(n0 + row) * K + kt + c4);
                Bs[c4 + 0][row] = f2tf(v.x);
                Bs[c4 + 1][row] = f2tf(v.y);
                Bs[c4 + 2][row] = f2tf(v.z);
                Bs[c4 + 3][row] = f2tf(v.w);
            }
        } else {
            // B is [K,N] row-major: 32 k-rows of 128 floats.
#pragma unroll
            for (int i = 0; i < 4; i++) {
                int linear = i * 256 + tid;       // 0..1023 (= 32 rows * 32 float4)
                int kr = linear >> 5;
                int c4 = (linear & 31) << 2;
                const float4 v = *(const float4*)(B + (size_t)(kt + kr) * N + n0 + c4);
                Bs[kr][c4 + 0] = f2tf(v.x);
                Bs[kr][c4 + 1] = f2tf(v.y);
                Bs[kr][c4 + 2] = f2tf(v.z);
                Bs[kr][c4 + 3] = f2tf(v.w);
            }
        }
        __syncthreads();

        // ---- compute: 4 k-steps of 8 ----
#pragma unroll
        for (int kk = 0; kk < BK; kk += 8) {
            unsigned af[4][4], bf[4][2];
#pragma unroll
            for (int mt = 0; mt < 4; mt++) {
                int rm = wr * 64 + mt * 16;
                af[mt][0] = As[kk + tig][rm + grp];
                af[mt][1] = As[kk + tig][rm + grp + 8];
                af[mt][2] = As[kk + tig + 4][rm + grp];
                af[mt][3] = As[kk + tig + 4][rm + grp + 8];
            }
#pragma unroll
            for (int nt = 0; nt < 4; nt++) {
                int cn = wc * 32 + nt * 8 + grp;
                bf[nt][0] = Bs[kk + tig][cn];
                bf[nt][1] = Bs[kk + tig + 4][cn];
            }
#pragma unroll
            for (int mt = 0; mt < 4; mt++)
#pragma unroll
                for (int nt = 0; nt < 4; nt++)
                    mma_tf32(acc[mt][nt], af[mt][0], af[mt][1], af[mt][2], af[mt][3],
                             bf[nt][0], bf[nt][1]);
        }
        __syncthreads();
    }

    // ---- epilogue: alpha * acc + bias ----
#pragma unroll
    for (int mt = 0; mt < 4; mt++) {
#pragma unroll
        for (int nt = 0; nt < 4; nt++) {
            int row = m0 + wr * 64 + mt * 16 + grp;
            int col = n0 + wc * 32 + nt * 8 + 2 * tig;
            float b0 = bias ? bias[col] : 0.0f;
            float b1 = bias ? bias[col + 1] : 0.0f;
            C[(size_t)row * N + col]           = alpha * acc[mt][nt][0] + b0;
            C[(size_t)row * N + col + 1]       = alpha * acc[mt][nt][1] + b1;
            C[(size_t)(row + 8) * N + col]     = alpha * acc[mt][nt][2] + b0;
            C[(size_t)(row + 8) * N + col + 1] = alpha * acc[mt][nt][3] + b1;
        }
    }
}

// Row softmax over rows of length 4096. One block (256 threads) per row;
// 16 elements per thread held in registers; two block reductions (max, sum).
__global__ void softmax_rows(float* __restrict__ S) {
    float* row = S + (size_t)blockIdx.x * 4096;
    const int tid  = threadIdx.x;
    const int lane = tid & 31;
    const int warp = tid >> 5;
    __shared__ float red[8];

    float v[16];
    float mx = -INFINITY;
#pragma unroll
    for (int i = 0; i < 4; i++) {
        float4 t = *(const float4*)(row + (size_t)(i * 256 + tid) * 4);
        v[i * 4 + 0] = t.x; v[i * 4 + 1] = t.y; v[i * 4 + 2] = t.z; v[i * 4 + 3] = t.w;
        mx = fmaxf(mx, fmaxf(fmaxf(t.x, t.y), fmaxf(t.z, t.w)));
    }
#pragma unroll
    for (int o = 16; o > 0; o >>= 1) mx = fmaxf(mx, __shfl_xor_sync(0xffffffffu, mx, o));
    if (lane == 0) red[warp] = mx;
    __syncthreads();
    float rowmax = red[0];
#pragma unroll
    for (int w = 1; w < 8; w++) rowmax = fmaxf(rowmax, red[w]);
    __syncthreads();

    float sum = 0.0f;
#pragma unroll
    for (int i = 0; i < 16; i++) {
        v[i] = __expf(v[i] - rowmax);
        sum += v[i];
    }
#pragma unroll
    for (int o = 16; o > 0; o >>= 1) sum += __shfl_xor_sync(0xffffffffu, sum, o);
    if (lane == 0) red[warp] = sum;
    __syncthreads();
    float tot = 0.0f;
#pragma unroll
    for (int w = 0; w < 8; w++) tot += red[w];
    float inv = 1.0f / tot;
#pragma unroll
    for (int i = 0; i < 4; i++) {
        float4 t;
        t.x = v[i * 4 + 0] * inv; t.y = v[i * 4 + 1] * inv;
        t.z = v[i * 4 + 2] * inv; t.w = v[i * 4 + 3] * inv;
        *(float4*)(row + (size_t)(i * 256 + tid) * 4) = t;
    }
}

extern "C" void kernel_launch(void* const* d_in, const int* in_sizes, int n_in,
                              void* d_out, int out_size) {
    const float* X  = (const float*)d_in[0];
    const float* Wq = (const float*)d_in[1];
    const float* Wk = (const float*)d_in[2];
    const float* Wv = (const float*)d_in[3];
    const float* bq = (const float*)d_in[4];
    const float* bk = (const float*)d_in[5];
    const float* bv = (const float*)d_in[6];
    float* O = (float*)d_out;

    float *Q, *K, *V, *S;
    cudaGetSymbolAddress((void**)&Q, g_Q);
    cudaGetSymbolAddress((void**)&K, g_K);
    cudaGetSymbolAddress((void**)&V, g_V);
    cudaGetSymbolAddress((void**)&S, g_S);

    const int Mqkv = 4 * 4096;   // 16384
    const int D    = 1024;
    const int N    = 4096;

    // 1) QKV projections: [16384,1024] x [1024,1024] + bias
    dim3 gQKV(D / BN, Mqkv / BM, 1);
    gemm_tf32<false><<<gQKV, 256>>>(X, Wq, bq, Q, Mqkv, D, D, 0, 0, 0, 1.0f);
    gemm_tf32<false><<<gQKV, 256>>>(X, Wk, bk, K, Mqkv, D, D, 0, 0, 0, 1.0f);
    gemm_tf32<false><<<gQKV, 256>>>(X, Wv, bv, V, Mqkv, D, D, 0, 0, 0, 1.0f);

    // 2) S = Q * K^T * (1/sqrt(1024)), batched over 4
    dim3 gS(N / BN, N / BM, 4);
    gemm_tf32<true><<<gS, 256>>>(Q, K, nullptr, S, N, N, D,
                                 (long long)N * D, (long long)N * D,
                                 (long long)N * N, 0.03125f);

    // 3) softmax in place: 16384 rows of 4096
    softmax_rows<<<4 * N, 256>>>(S);

    // 4) O = P * V, batched over 4
    dim3 gO(D / BN, N / BM, 4);
    gemm_tf32<false><<<gO, 256>>>(S, V, nullptr, O, N, D, N,
                                  (long long)N * N, (long long)N * D,
                                  (long long)N * D, 1.0f);
}

// round 3
// speedup vs baseline: 2.6239x; 2.6239x over previous
#include <cuda_runtime.h>
#include <cuda_fp16.h>
#include <cstdint>
#include <math.h>

// ---------------------------------------------------------------------------
// SelfAttention B=4, N=4096, d=1024, fp32 in/out, rel_err < 1e-3.
// fp16 tensor-core path (same 11-bit mantissa as tf32):
//   0) convert X -> fp16; transpose+convert Wq/Wk/Wv -> fp16 [N][K]
//   1) gemm_tn: Q/K/V = Xh * Wt^T + b   (fp16 out)
//   2) transpose Vh -> Vt [e][n] fp16
//   3) gemm_tn: S = Qh * Kh^T * 1/32    (fp32 out)
//   4) softmax rows of S -> P (fp16)
//   5) gemm_tn: O = P * Vt^T            (fp32 out = d_out)
// One TN GEMM kernel: A[m][k] * B[n][k]^T, cp.async 3-stage pipeline,
// m16n8k16 HMMA, warp tile 64x64, conflict-free 80B smem rows.
// ---------------------------------------------------------------------------

#define BM 128
#define BN 256
#define BK 32
#define STAGES 3
#define ROWH 40            // halfs per smem row: 32 data + 8 pad = 80 bytes
#define THREADS 256

// fp16 scratch
__device__ __half g_Xh[(size_t)4 * 4096 * 1024];
__device__ __half g_Wt[3][1024 * 1024];
__device__ __half g_Qh[(size_t)4 * 4096 * 1024];
__device__ __half g_Kh[(size_t)4 * 4096 * 1024];
__device__ __half g_Vh[(size_t)4 * 4096 * 1024];
__device__ __half g_Vt[(size_t)4 * 4096 * 1024];
__device__ float  g_S [(size_t)4 * 4096 * 4096];
__device__ __half g_P [(size_t)4 * 4096 * 4096];

// ---------------- async copy helpers ----------------
__device__ __forceinline__ void cp16(void* smem, const void* gmem) {
    uint32_t s = (uint32_t)__cvta_generic_to_shared(smem);
    asm volatile("cp.async.cg.shared.global [%0], [%1], 16;\n" :: "r"(s), "l"(gmem));
}
__device__ __forceinline__ void cp_commit() { asm volatile("cp.async.commit_group;\n"); }
template <int N> __device__ __forceinline__ void cp_wait() {
    asm volatile("cp.async.wait_group %0;\n" :: "n"(N));
}

__device__ __forceinline__ void mma16816(float c[4], const uint32_t a[4], const uint32_t b[2]) {
    asm volatile(
        "mma.sync.aligned.m16n8k16.row.col.f32.f16.f16.f32 "
        "{%0,%1,%2,%3},{%4,%5,%6,%7},{%8,%9},{%0,%1,%2,%3};"
        : "+f"(c[0]), "+f"(c[1]), "+f"(c[2]), "+f"(c[3])
        : "r"(a[0]), "r"(a[1]), "r"(a[2]), "r"(a[3]), "r"(b[0]), "r"(b[1]));
}

// epilogue stores: 2 adjacent columns
__device__ __forceinline__ void store2(__half* C, size_t idx, float v0, float v1) {
    *(__half2*)(C + idx) = __floats2half2_rn(v0, v1);
}
__device__ __forceinline__ void store2(float* C, size_t idx, float v0, float v1) {
    float2 t; t.x = v0; t.y = v1;
    *(float2*)(C + idx) = t;
}

// ---------------- TN GEMM: C[m][n] = alpha * sum_k A[m][k]*B[n][k] + bias[n] ----
template <typename OutT>
__global__ void __launch_bounds__(THREADS)
gemm_tn(const __half* __restrict__ A, const __half* __restrict__ B,
        const float* __restrict__ bias, OutT* __restrict__ C,
        int N, int K, long long strA, long long strB, long long strC, float alpha) {
    extern __shared__ __half sm[];
    __half* sA = sm;                                  // STAGES*BM*ROWH
    __half* sB = sm + STAGES * BM * ROWH;             // STAGES*BN*ROWH

    A += (long long)blockIdx.z * strA;
    B += (long long)blockIdx.z * strB;
    C += (long long)blockIdx.z * strC;

    const int tid  = threadIdx.x;
    const int lane = tid & 31;
    const int warp = tid >> 5;        // 8 warps: 2 (M) x 4 (N)
    const int wr   = warp & 1;
    const int wc   = warp >> 1;
    const int grp  = lane >> 2;
    const int tig  = lane & 3;

    const int m0 = blockIdx.y * BM;
    const int n0 = blockIdx.x * BN;

    float acc[4][8][4];
#pragma unroll
    for (int i = 0; i < 4; i++)
#pragma unroll
        for (int j = 0; j < 8; j++)
#pragma unroll
            for (int v = 0; v < 4; v++) acc[i][j][v] = 0.0f;

    const int ktiles = K / BK;

    // stage loaders: A = 512 chunks (2/thread), B = 1024 chunks (4/thread)
    auto loadA = [&](int st, int kt) {
#pragma unroll
        for (int i = 0; i < 2; i++) {
            int c   = i * THREADS + tid;
            int row = c >> 2, ch = c & 3;
            cp16(sA + (size_t)st * BM * ROWH + row * ROWH + ch * 8,
                 A + (size_t)(m0 + row) * K + kt + ch * 8);
        }
    };
    auto loadB = [&](int st, int kt) {
#pragma unroll
        for (int i = 0; i < 4; i++) {
            int c   = i * THREADS + tid;
            int row = c >> 2, ch = c & 3;
            cp16(sB + (size_t)st * BN * ROWH + row * ROWH + ch * 8,
                 B + (size_t)(n0 + row) * K + kt + ch * 8);
        }
    };

    loadA(0, 0); loadB(0, 0); cp_commit();
    loadA(1, BK); loadB(1, BK); cp_commit();

    for (int kt = 0; kt < ktiles; kt++) {
        cp_wait<1>();
        __syncthreads();

        if (kt + 2 < ktiles) {
            int ns = (kt + 2) % STAGES;
            loadA(ns, (kt + 2) * BK);
            loadB(ns, (kt + 2) * BK);
        }
        cp_commit();

        const __half* cA = sA + (size_t)(kt % STAGES) * BM * ROWH;
        const __half* cB = sB + (size_t)(kt % STAGES) * BN * ROWH;

#pragma unroll
        for (int kk = 0; kk < BK; kk += 16) {
            uint32_t af[4][4];
#pragma unroll
            for (int mt = 0; mt < 4; mt++) {
                const __half* p = cA + (wr * 64 + mt * 16 + grp) * ROWH + kk + 2 * tig;
                af[mt][0] = *(const uint32_t*)(p);
                af[mt][1] = *(const uint32_t*)(p + 8 * ROWH);
                af[mt][2] = *(const uint32_t*)(p + 8);
                af[mt][3] = *(const uint32_t*)(p + 8 * ROWH + 8);
            }
            uint32_t bf[8][2];
#pragma unroll
            for (int nt = 0; nt < 8; nt++) {
                const __half* p = cB + (wc * 64 + nt * 8 + grp) * ROWH + kk + 2 * tig;
                bf[nt][0] = *(const uint32_t*)(p);
                bf[nt][1] = *(const uint32_t*)(p + 8);
            }
#pragma unroll
            for (int mt = 0; mt < 4; mt++)
#pragma unroll
                for (int nt = 0; nt < 8; nt++) mma16816(acc[mt][nt], af[mt], bf[nt]);
        }
        __syncthreads();
    }

    // epilogue
#pragma unroll
    for (int mt = 0; mt < 4; mt++) {
#pragma unroll
        for (int nt = 0; nt < 8; nt++) {
            int row = m0 + wr * 64 + mt * 16 + grp;
            int col = n0 + wc * 64 + nt * 8 + 2 * tig;
            float b0 = 0.0f, b1 = 0.0f;
            if (bias) { b0 = bias[col]; b1 = bias[col + 1]; }
            float* c = acc[mt][nt];
            store2(C, (size_t)row * N + col,       alpha * c[0] + b0, alpha * c[1] + b1);
            store2(C, (size_t)(row + 8) * N + col, alpha * c[2] + b0, alpha * c[3] + b1);
        }
    }
}

// ---------------- converts / transposes ----------------
__global__ void f2h_kernel(const float* __restrict__ in, __half* __restrict__ out, size_t n) {
    size_t i = ((size_t)blockIdx.x * blockDim.x + threadIdx.x) * 4;
    if (i < n) {
        float4 v = *(const float4*)(in + i);
        __half2* o = (__half2*)(out + i);
        o[0] = __floats2half2_rn(v.x, v.y);
        o[1] = __floats2half2_rn(v.z, v.w);
    }
}

// in: fp32 [R][C] -> out: fp16 [C][R]
__global__ void tr_f2h(const float* __restrict__ in, __half* __restrict__ out, int R, int C) {
    __shared__ float t[32][33];
    int c0 = blockIdx.x * 32, r0 = blockIdx.y * 32;
#pragma unroll
    for (int i = threadIdx.y; i < 32; i += 8)
        t[i][threadIdx.x] = in[(size_t)(r0 + i) * C + c0 + threadIdx.x];
    __syncthreads();
#pragma unroll
    for (int i = threadIdx.y; i < 32; i += 8)
        out[(size_t)(c0 + i) * R + r0 + threadIdx.x] = __float2half(t[threadIdx.x][i]);
}

// in: fp16 [R][C] -> out: fp16 [C][R], batched by blockIdx.z (stride R*C)
__global__ void tr_h(const __half* __restrict__ in, __half* __restrict__ out, int R, int C) {
    in  += (size_t)blockIdx.z * R * C;
    out += (size_t)blockIdx.z * R * C;
    __shared__ __half t[32][33];
    int c0 = blockIdx.x * 32, r0 = blockIdx.y * 32;
#pragma unroll
    for (int i = threadIdx.y; i < 32; i += 8)
        t[i][threadIdx.x] = in[(size_t)(r0 + i) * C + c0 + threadIdx.x];
    __syncthreads();
#pragma unroll
    for (int i = threadIdx.y; i < 32; i += 8)
        out[(size_t)(c0 + i) * R + r0 + threadIdx.x] = t[threadIdx.x][i];
}

// ---------------- softmax: rows of 4096, fp32 in -> fp16 out ----------------
__global__ void softmax_rows(const float* __restrict__ S, __half* __restrict__ P) {
    const float* row = S + (size_t)blockIdx.x * 4096;
    __half* prow     = P + (size_t)blockIdx.x * 4096;
    const int tid  = threadIdx.x;
    const int lane = tid & 31;
    const int warp = tid >> 5;
    __shared__ float red[8];

    float v[16];
    float mx = -INFINITY;
#pragma unroll
    for (int i = 0; i < 4; i++) {
        float4 t = *(const float4*)(row + (size_t)(i * 256 + tid) * 4);
        v[i * 4 + 0] = t.x; v[i * 4 + 1] = t.y; v[i * 4 + 2] = t.z; v[i * 4 + 3] = t.w;
        mx = fmaxf(mx, fmaxf(fmaxf(t.x, t.y), fmaxf(t.z, t.w)));
    }
#pragma unroll
    for (int o = 16; o > 0; o >>= 1) mx = fmaxf(mx, __shfl_xor_sync(0xffffffffu, mx, o));
    if (lane == 0) red[warp] = mx;
    __syncthreads();
    float rowmax = red[0];
#pragma unroll
    for (int w = 1; w < 8; w++) rowmax = fmaxf(rowmax, red[w]);
    __syncthreads();

    float sum = 0.0f;
#pragma unroll
    for (int i = 0; i < 16; i++) { v[i] = __expf(v[i] - rowmax); sum += v[i]; }
#pragma unroll
    for (int o = 16; o > 0; o >>= 1) sum += __shfl_xor_sync(0xffffffffu, sum, o);
    if (lane == 0) red[warp] = sum;
    __syncthreads();
    float tot = 0.0f;
#pragma unroll
    for (int w = 0; w < 8; w++) tot += red[w];
    float inv = 1.0f / tot;
#pragma unroll
    for (int i = 0; i < 4; i++) {
        size_t idx = (size_t)(i * 256 + tid) * 4;
        __half2* o = (__half2*)(prow + idx);
        o[0] = __floats2half2_rn(v[i * 4 + 0] * inv, v[i * 4 + 1] * inv);
        o[1] = __floats2half2_rn(v[i * 4 + 2] * inv, v[i * 4 + 3] * inv);
    }
}

// ---------------- launch ----------------
extern "C" void kernel_launch(void* const* d_in, const int* in_sizes, int n_in,
                              void* d_out, int out_size) {
    const float* X  = (const float*)d_in[0];
    const float* Wq = (const float*)d_in[1];
    const float* Wk = (const float*)d_in[2];
    const float* Wv = (const float*)d_in[3];
    const float* bq = (const float*)d_in[4];
    const float* bk = (const float*)d_in[5];
    const float* bv = (const float*)d_in[6];
    float* O = (float*)d_out;

    __half *Xh, *Wt, *Qh, *Kh, *Vh, *Vt, *P;
    float* S;
    cudaGetSymbolAddress((void**)&Xh, g_Xh);
    cudaGetSymbolAddress((void**)&Wt, g_Wt);
    cudaGetSymbolAddress((void**)&Qh, g_Qh);
    cudaGetSymbolAddress((void**)&Kh, g_Kh);
    cudaGetSymbolAddress((void**)&Vh, g_Vh);
    cudaGetSymbolAddress((void**)&Vt, g_Vt);
    cudaGetSymbolAddress((void**)&S,  g_S);
    cudaGetSymbolAddress((void**)&P,  g_P);

    const int D = 1024, N = 4096;
    const size_t SMEM = (size_t)STAGES * (BM + BN) * ROWH * sizeof(__half);  // 92160

    static int attr_done = 0;
    if (!attr_done) {
        cudaFuncSetAttribute(gemm_tn<__half>, cudaFuncAttributeMaxDynamicSharedMemorySize, (int)SMEM);
        cudaFuncSetAttribute(gemm_tn<float>,  cudaFuncAttributeMaxDynamicSharedMemorySize, (int)SMEM);
        attr_done = 1;
    }

    // 0) convert X; transpose-convert Ws
    {
        size_t n = (size_t)4 * N * D;
        f2h_kernel<<<(unsigned)(n / 4 / 256), 256>>>(X, Xh, n);
        dim3 b(32, 8), g(D / 32, D / 32);
        tr_f2h<<<g, b>>>(Wq, Wt + 0 * (size_t)D * D, D, D);
        tr_f2h<<<g, b>>>(Wk, Wt + 1 * (size_t)D * D, D, D);
        tr_f2h<<<g, b>>>(Wv, Wt + 2 * (size_t)D * D, D, D);
    }

    // 1) QKV projections (fp16 out)
    {
        dim3 g(D / BN, 4 * N / BM, 1);
        gemm_tn<__half><<<g, THREADS, SMEM>>>(Xh, Wt + 0 * (size_t)D * D, bq, Qh, D, D, 0, 0, 0, 1.0f);
        gemm_tn<__half><<<g, THREADS, SMEM>>>(Xh, Wt + 1 * (size_t)D * D, bk, Kh, D, D, 0, 0, 0, 1.0f);
        gemm_tn<__half><<<g, THREADS, SMEM>>>(Xh, Wt + 2 * (size_t)D * D, bv, Vh, D, D, 0, 0, 0, 1.0f);
    }

    // 2) V transpose per batch: [4096][1024] -> [1024][4096]
    {
        dim3 b(32, 8), g(D / 32, N / 32, 4);
        tr_h<<<g, b>>>(Vh, Vt, N, D);
    }

    // 3) S = Q K^T / 32 (fp32 out)
    {
        dim3 g(N / BN, N / BM, 4);
        gemm_tn<float><<<g, THREADS, SMEM>>>(Qh, Kh, nullptr, S, N, D,
                                             (long long)N * D, (long long)N * D,
                                             (long long)N * N, 0.03125f);
    }

    // 4) softmax -> P fp16
    softmax_rows<<<4 * N, 256>>>(S, P);

    // 5) O = P Vt^T (fp32 out)
    {
        dim3 g(D / BN, N / BM, 4);
        gemm_tn<float><<<g, THREADS, SMEM>>>(P, Vt, nullptr, O, D, N,
                                             (long long)N * N, (long long)N * D,
                                             (long long)N * D, 1.0f);
    }
}

// round 6
// speedup vs baseline: 3.6564x; 1.3935x over previous
#include <cuda_runtime.h>
#include <cuda_fp16.h>
#include <cstdint>
#include <math.h>

// ---------------------------------------------------------------------------
// SelfAttention B=4, N=4096, d=1024, fp32 in/out, rel_err < 1e-3.
// Legacy mma.sync fp16 path (tcgen05 unavailable: harness targets sm_100).
//   0) X -> fp16; W* -> transposed fp16 (contiguous [3072][1024])
//   1) fused QKV = Xh * Wcat^T + b   (one GEMM, N=3072, split outputs)
//   2) Vh -> Vt transpose
//   3) S = Qh * Kh^T / 32            (fp16 out)
//   4) softmax rows -> P fp16
//   5) O = P * Vt^T                  (fp32 out)
// GEMM: BM=128 BN=256 BK=64, SW128-swizzled smem, cp.async 3-stage,
// ldmatrix.x4 fragment loads, m16n8k16 HMMA, warp tile 64x64.
// ---------------------------------------------------------------------------

#define THREADS 256
#define A_STG 16384                   // 128 rows * 128B
#define B_STG 32768                   // 256 rows * 128B
#define OFF_B (3 * A_STG)             // 49152
#define SMEM_TOTAL (3 * A_STG + 3 * B_STG)   // 147456

#define SWZ(o) ((o) ^ (((o) >> 3) & 0x70))

// scratch
__device__ __half g_Xh[(size_t)4 * 4096 * 1024];
__device__ __half g_Wt[3ull * 1024 * 1024];        // [3072][1024] (Q,K,V concat)
__device__ __half g_Qh[(size_t)4 * 4096 * 1024];
__device__ __half g_Kh[(size_t)4 * 4096 * 1024];
__device__ __half g_Vh[(size_t)4 * 4096 * 1024];
__device__ __half g_Vt[(size_t)4 * 4096 * 1024];
__device__ __half g_S [(size_t)4 * 4096 * 4096];
__device__ __half g_P [(size_t)4 * 4096 * 4096];

// ---------------- PTX helpers ----------------
__device__ __forceinline__ uint32_t smem_u32(const void* p) {
    uint32_t a;
    asm("{ .reg .u64 t; cvta.to.shared.u64 t, %1; cvt.u32.u64 %0, t; }" : "=r"(a) : "l"(p));
    return a;
}
__device__ __forceinline__ void cp16s(uint32_t s, const void* g) {
    asm volatile("cp.async.cg.shared.global [%0], [%1], 16;\n" :: "r"(s), "l"(g));
}
__device__ __forceinline__ void cp_commit() { asm volatile("cp.async.commit_group;\n"); }
template <int N> __device__ __forceinline__ void cp_wait() {
    asm volatile("cp.async.wait_group %0;\n" :: "n"(N));
}
__device__ __forceinline__ void ldsm4(uint32_t* r, uint32_t addr) {
    asm volatile("ldmatrix.sync.aligned.m8n8.x4.shared.b16 {%0,%1,%2,%3}, [%4];"
        : "=r"(r[0]), "=r"(r[1]), "=r"(r[2]), "=r"(r[3]) : "r"(addr));
}
__device__ __forceinline__ void mma16816(float c[4], const uint32_t a[4], const uint32_t b[2]) {
    asm volatile(
        "mma.sync.aligned.m16n8k16.row.col.f32.f16.f16.f32 "
        "{%0,%1,%2,%3},{%4,%5,%6,%7},{%8,%9},{%0,%1,%2,%3};"
        : "+f"(c[0]), "+f"(c[1]), "+f"(c[2]), "+f"(c[3])
        : "r"(a[0]), "r"(a[1]), "r"(a[2]), "r"(a[3]), "r"(b[0]), "r"(b[1]));
}

__device__ __forceinline__ void store2(__half* C, size_t idx, float v0, float v1) {
    *(__half2*)(C + idx) = __floats2half2_rn(v0, v1);
}
__device__ __forceinline__ void store2(float* C, size_t idx, float v0, float v1) {
    float2 t; t.x = v0; t.y = v1;
    *(float2*)(C + idx) = t;
}

// ---------------- TN GEMM ----------------
// C[m][n] = alpha * sum_k A[m][k]*B[n][k] + bias[n].
// Output columns split into segments of Nout (for fused QKV); seg = n0/Nout
// selects (C0,b0) / (C1,b1) / (C2,b2). Batched over blockIdx.z.
template <typename OutT>
__global__ void __launch_bounds__(THREADS, 1)
gemm_tn(const __half* __restrict__ A, const __half* __restrict__ B,
        const float* b0p, const float* b1p, const float* b2p,
        OutT* C0, OutT* C1, OutT* C2,
        int Nout, int K, long long strA, long long strB, long long strC, float alpha) {
    extern __shared__ __align__(128) char smem[];
    const uint32_t sb = smem_u32(smem);

    A += (long long)blockIdx.z * strA;
    B += (long long)blockIdx.z * strB;

    const int tid  = threadIdx.x;
    const int lane = tid & 31;
    const int warp = tid >> 5;        // 8 warps: 2 (M) x 4 (N)
    const int wr   = warp & 1;
    const int wc   = warp >> 1;
    const int grp  = lane >> 2;
    const int tig  = lane & 3;

    const int m0 = blockIdx.y * 128;
    const int n0 = blockIdx.x * 256;

    const int seg = n0 / Nout;
    const int nc0 = n0 - seg * Nout;
    OutT* C = (seg == 0) ? C0 : (seg == 1) ? C1 : C2;
    const float* bias = (seg == 0) ? b0p : (seg == 1) ? b1p : b2p;
    C += (long long)blockIdx.z * strC;

    float acc[4][8][4];
#pragma unroll
    for (int i = 0; i < 4; i++)
#pragma unroll
        for (int j = 0; j < 8; j++)
#pragma unroll
            for (int v = 0; v < 4; v++) acc[i][j][v] = 0.0f;

    auto aS = [&](int s) -> uint32_t { return sb + s * A_STG; };
    auto bS = [&](int s) -> uint32_t { return sb + OFF_B + s * B_STG; };

    auto loadA = [&](int s, int kt) {
#pragma unroll
        for (int i = 0; i < 4; i++) {
            int c = i * THREADS + tid;        // 1024 16B chunks
            int row = c >> 3, ch = c & 7;
            cp16s(aS(s) + SWZ(row * 128 + ch * 16),
                  A + (size_t)(m0 + row) * K + kt * 64 + ch * 8);
        }
    };
    auto loadB = [&](int s, int kt) {
#pragma unroll
        for (int i = 0; i < 8; i++) {
            int c = i * THREADS + tid;        // 2048 16B chunks
            int row = c >> 3, ch = c & 7;
            cp16s(bS(s) + SWZ(row * 128 + ch * 16),
                  B + (size_t)(n0 + row) * K + kt * 64 + ch * 8);
        }
    };

    const int ktiles = K / 64;
    loadA(0, 0); loadB(0, 0); cp_commit();
    loadA(1, 1); loadB(1, 1); cp_commit();

    // per-thread ldmatrix lane offsets
    const int a_row = lane & 15;                      // row within 16
    const int a_ko  = (lane >> 4) << 4;               // 0 / 16 bytes
    const int b_row = (lane & 7) + ((lane >> 4) << 3);// row within 16
    const int b_ko  = ((lane >> 3) & 1) << 4;         // 0 / 16 bytes
    const int rm = wr * 64;
    const int nb = wc * 64;

    for (int kt = 0; kt < ktiles; kt++) {
        cp_wait<1>();
        __syncthreads();

        if (kt + 2 < ktiles) {
            int ns = (kt + 2) % 3;
            loadA(ns, kt + 2);
            loadB(ns, kt + 2);
        }
        cp_commit();

        const uint32_t cA = aS(kt % 3);
        const uint32_t cB = bS(kt % 3);

#pragma unroll
        for (int st = 0; st < 4; st++) {
            const int kkb = st * 32;                  // byte offset of k16 step
            uint32_t af[4][4];
#pragma unroll
            for (int mt = 0; mt < 4; mt++)
                ldsm4(af[mt], cA + SWZ((rm + mt * 16 + a_row) * 128 + kkb + a_ko));
            uint32_t bf[8][2];
#pragma unroll
            for (int j = 0; j < 4; j++) {
                uint32_t t[4];
                ldsm4(t, cB + SWZ((nb + j * 16 + b_row) * 128 + kkb + b_ko));
                bf[2 * j][0] = t[0]; bf[2 * j][1] = t[1];
                bf[2 * j + 1][0] = t[2]; bf[2 * j + 1][1] = t[3];
            }
#pragma unroll
            for (int mt = 0; mt < 4; mt++)
#pragma unroll
                for (int nt = 0; nt < 8; nt++) mma16816(acc[mt][nt], af[mt], bf[nt]);
        }
        __syncthreads();
    }

    // epilogue
#pragma unroll
    for (int mt = 0; mt < 4; mt++) {
#pragma unroll
        for (int nt = 0; nt < 8; nt++) {
            int row = m0 + wr * 64 + mt * 16 + grp;
            int col = nc0 + wc * 64 + nt * 8 + 2 * tig;
            float bb0 = 0.0f, bb1 = 0.0f;
            if (bias) { bb0 = bias[col]; bb1 = bias[col + 1]; }
            float* c = acc[mt][nt];
            store2(C, (size_t)row * Nout + col,       alpha * c[0] + bb0, alpha * c[1] + bb1);
            store2(C, (size_t)(row + 8) * Nout + col, alpha * c[2] + bb0, alpha * c[3] + bb1);
        }
    }
}

// ---------------- converts / transposes ----------------
__global__ void f2h_kernel(const float* __restrict__ in, __half* __restrict__ out, size_t n) {
    size_t i = ((size_t)blockIdx.x * blockDim.x + threadIdx.x) * 4;
    if (i < n) {
        float4 v = *(const float4*)(in + i);
        __half2* o = (__half2*)(out + i);
        o[0] = __floats2half2_rn(v.x, v.y);
        o[1] = __floats2half2_rn(v.z, v.w);
    }
}

__global__ void tr_f2h(const float* __restrict__ in, __half* __restrict__ out, int R, int C) {
    __shared__ float t[32][33];
    int c0 = blockIdx.x * 32, r0 = blockIdx.y * 32;
#pragma unroll
    for (int i = threadIdx.y; i < 32; i += 8)
        t[i][threadIdx.x] = in[(size_t)(r0 + i) * C + c0 + threadIdx.x];
    __syncthreads();
#pragma unroll
    for (int i = threadIdx.y; i < 32; i += 8)
        out[(size_t)(c0 + i) * R + r0 + threadIdx.x] = __float2half(t[threadIdx.x][i]);
}

__global__ void tr_h(const __half* __restrict__ in, __half* __restrict__ out, int R, int C) {
    in  += (size_t)blockIdx.z * R * C;
    out += (size_t)blockIdx.z * R * C;
    __shared__ __half t[32][33];
    int c0 = blockIdx.x * 32, r0 = blockIdx.y * 32;
#pragma unroll
    for (int i = threadIdx.y; i < 32; i += 8)
        t[i][threadIdx.x] = in[(size_t)(r0 + i) * C + c0 + threadIdx.x];
    __syncthreads();
#pragma unroll
    for (int i = threadIdx.y; i < 32; i += 8)
        out[(size_t)(c0 + i) * R + r0 + threadIdx.x] = t[threadIdx.x][i];
}

// ---------------- softmax: rows of 4096 fp16 -> fp16 ----------------
__global__ void softmax_rows(const __half* __restrict__ S, __half* __restrict__ P) {
    const __half* row = S + (size_t)blockIdx.x * 4096;
    __half* prow      = P + (size_t)blockIdx.x * 4096;
    const int tid  = threadIdx.x;
    const int lane = tid & 31;
    const int warp = tid >> 5;
    __shared__ float red[8];

    float v[16];
    float mx = -INFINITY;
#pragma unroll
    for (int i = 0; i < 2; i++) {
        uint4 u = ((const uint4*)row)[i * 256 + tid];
        const uint32_t* w = (const uint32_t*)&u;
#pragma unroll
        for (int j = 0; j < 4; j++) {
            float2 f = __half22float2(*(const __half2*)&w[j]);
            v[i * 8 + 2 * j] = f.x; v[i * 8 + 2 * j + 1] = f.y;
            mx = fmaxf(mx, fmaxf(f.x, f.y));
        }
    }
#pragma unroll
    for (int o = 16; o > 0; o >>= 1) mx = fmaxf(mx, __shfl_xor_sync(0xffffffffu, mx, o));
    if (lane == 0) red[warp] = mx;
    __syncthreads();
    float rowmax = red[0];
#pragma unroll
    for (int w = 1; w < 8; w++) rowmax = fmaxf(rowmax, red[w]);
    __syncthreads();

    float sum = 0.0f;
#pragma unroll
    for (int i = 0; i < 16; i++) { v[i] = __expf(v[i] - rowmax); sum += v[i]; }
#pragma unroll
    for (int o = 16; o > 0; o >>= 1) sum += __shfl_xor_sync(0xffffffffu, sum, o);
    if (lane == 0) red[warp] = sum;
    __syncthreads();
    float tot = 0.0f;
#pragma unroll
    for (int w = 0; w < 8; w++) tot += red[w];
    float inv = 1.0f / tot;
#pragma unroll
    for (int i = 0; i < 2; i++) {
        uint4 u;
        uint32_t* w = (uint32_t*)&u;
#pragma unroll
        for (int j = 0; j < 4; j++) {
            __half2 h = __floats2half2_rn(v[i * 8 + 2 * j] * inv, v[i * 8 + 2 * j + 1] * inv);
            w[j] = *(const uint32_t*)&h;
        }
        ((uint4*)prow)[i * 256 + tid] = u;
    }
}

// ---------------- launch ----------------
extern "C" void kernel_launch(void* const* d_in, const int* in_sizes, int n_in,
                              void* d_out, int out_size) {
    const float* X  = (const float*)d_in[0];
    const float* Wq = (const float*)d_in[1];
    const float* Wk = (const float*)d_in[2];
    const float* Wv = (const float*)d_in[3];
    const float* bq = (const float*)d_in[4];
    const float* bk = (const float*)d_in[5];
    const float* bv = (const float*)d_in[6];
    float* O = (float*)d_out;

    __half *Xh, *Wt, *Qh, *Kh, *Vh, *Vt, *S, *P;
    cudaGetSymbolAddress((void**)&Xh, g_Xh);
    cudaGetSymbolAddress((void**)&Wt, g_Wt);
    cudaGetSymbolAddress((void**)&Qh, g_Qh);
    cudaGetSymbolAddress((void**)&Kh, g_Kh);
    cudaGetSymbolAddress((void**)&Vh, g_Vh);
    cudaGetSymbolAddress((void**)&Vt, g_Vt);
    cudaGetSymbolAddress((void**)&S,  g_S);
    cudaGetSymbolAddress((void**)&P,  g_P);

    const int D = 1024, N = 4096;

    static int attr_done = 0;
    if (!attr_done) {
        cudaFuncSetAttribute(gemm_tn<__half>, cudaFuncAttributeMaxDynamicSharedMemorySize, SMEM_TOTAL);
        cudaFuncSetAttribute(gemm_tn<float>,  cudaFuncAttributeMaxDynamicSharedMemorySize, SMEM_TOTAL);
        attr_done = 1;
    }

    // 0) converts
    {
        size_t n = (size_t)4 * N * D;
        f2h_kernel<<<(unsigned)(n / 4 / 256), 256>>>(X, Xh, n);
        dim3 b(32, 8), g(D / 32, D / 32);
        tr_f2h<<<g, b>>>(Wq, Wt + 0ull * D * D, D, D);
        tr_f2h<<<g, b>>>(Wk, Wt + 1ull * D * D, D, D);
        tr_f2h<<<g, b>>>(Wv, Wt + 2ull * D * D, D, D);
    }

    // 1) fused QKV: [16384,1024] x [3072,1024]^T, split into Q/K/V
    {
        dim3 g(3 * D / 256, 4 * N / 128, 1);
        gemm_tn<__half><<<g, THREADS, SMEM_TOTAL>>>(
            Xh, Wt, bq, bk, bv, Qh, Kh, Vh, D, D, 0, 0, 0, 1.0f);
    }

    // 2) V transpose per batch
    {
        dim3 b(32, 8), g(D / 32, N / 32, 4);
        tr_h<<<g, b>>>(Vh, Vt, N, D);
    }

    // 3) S = Q K^T / 32 (fp16 out)
    {
        dim3 g(N / 256, N / 128, 4);
        gemm_tn<__half><<<g, THREADS, SMEM_TOTAL>>>(
            Qh, Kh, nullptr, nullptr, nullptr, S, nullptr, nullptr,
            N, D, (long long)N * D, (long long)N * D, (long long)N * N, 0.03125f);
    }

    // 4) softmax -> P
    softmax_rows<<<4 * N, 256>>>(S, P);

    // 5) O = P Vt^T (fp32 out)
    {
        dim3 g(D / 256, N / 128, 4);
        gemm_tn<float><<<g, THREADS, SMEM_TOTAL>>>(
            P, Vt, nullptr, nullptr, nullptr, O, nullptr, nullptr,
            D, N, (long long)N * N, (long long)N * D, (long long)N * D, 1.0f);
    }
}

// round 7
// speedup vs baseline: 3.7934x; 1.0375x over previous
#include <cuda_runtime.h>
#include <cuda_fp16.h>
#include <cstdint>
#include <math.h>

// ---------------------------------------------------------------------------
// SelfAttention B=4, N=4096, d=1024, fp32 in/out, rel_err < 1e-3.
// mma.sync fp16 path. Softmax folded into GEMM epilogues:
//   0) X -> fp16; W* -> transposed fp16 (contiguous [3072][1024])
//   1) fused QKV = Xh * Wcat^T + b     (MODE0, fp16 out)
//   2) Vh -> Vt transpose
//   3) P = exp(Q K^T / 32)             (MODE1: exp in epilogue, Z row sums
//                                       via atomicAdd; no softmax kernel)
//   4) O = (P Vt^T) / Z                (MODE2: normalize in epilogue)
// GEMM: BM=128 BN=256 BK=64, SW128 smem, cp.async 3-stage, ldmatrix.x4,
// ONE barrier per k-tile, m-on-x raster for B-tile L2 reuse.
// ---------------------------------------------------------------------------

#define THREADS 256
#define A_STG 16384                   // 128 rows * 128B
#define B_STG 32768                   // 256 rows * 128B
#define OFF_B (3 * A_STG)             // 49152
#define SMEM_TOTAL (3 * A_STG + 3 * B_STG)   // 147456

#define SWZ(o) ((o) ^ (((o) >> 3) & 0x70))

// scratch
__device__ __half g_Xh[(size_t)4 * 4096 * 1024];
__device__ __half g_Wt[3ull * 1024 * 1024];        // [3072][1024] (Q,K,V concat)
__device__ __half g_Qh[(size_t)4 * 4096 * 1024];
__device__ __half g_Kh[(size_t)4 * 4096 * 1024];
__device__ __half g_Vh[(size_t)4 * 4096 * 1024];
__device__ __half g_Vt[(size_t)4 * 4096 * 1024];
__device__ __half g_S [(size_t)4 * 4096 * 4096];   // holds un-normalized exp(S)
__device__ float  g_Z [4 * 4096];                  // row sums of exp(S)

// ---------------- PTX helpers ----------------
__device__ __forceinline__ uint32_t smem_u32(const void* p) {
    uint32_t a;
    asm("{ .reg .u64 t; cvta.to.shared.u64 t, %1; cvt.u32.u64 %0, t; }" : "=r"(a) : "l"(p));
    return a;
}
__device__ __forceinline__ void cp16s(uint32_t s, const void* g) {
    asm volatile("cp.async.cg.shared.global [%0], [%1], 16;\n" :: "r"(s), "l"(g));
}
__device__ __forceinline__ void cp_commit() { asm volatile("cp.async.commit_group;\n"); }
template <int N> __device__ __forceinline__ void cp_wait() {
    asm volatile("cp.async.wait_group %0;\n" :: "n"(N));
}
__device__ __forceinline__ void ldsm4(uint32_t* r, uint32_t addr) {
    asm volatile("ldmatrix.sync.aligned.m8n8.x4.shared.b16 {%0,%1,%2,%3}, [%4];"
        : "=r"(r[0]), "=r"(r[1]), "=r"(r[2]), "=r"(r[3]) : "r"(addr));
}
__device__ __forceinline__ void mma16816(float c[4], const uint32_t a[4], const uint32_t b[2]) {
    asm volatile(
        "mma.sync.aligned.m16n8k16.row.col.f32.f16.f16.f32 "
        "{%0,%1,%2,%3},{%4,%5,%6,%7},{%8,%9},{%0,%1,%2,%3};"
        : "+f"(c[0]), "+f"(c[1]), "+f"(c[2]), "+f"(c[3])
        : "r"(a[0]), "r"(a[1]), "r"(a[2]), "r"(a[3]), "r"(b[0]), "r"(b[1]));
}

__device__ __forceinline__ void store2(__half* C, size_t idx, float v0, float v1) {
    *(__half2*)(C + idx) = __floats2half2_rn(v0, v1);
}
__device__ __forceinline__ void store2(float* C, size_t idx, float v0, float v1) {
    float2 t; t.x = v0; t.y = v1;
    *(float2*)(C + idx) = t;
}

// ---------------- TN GEMM ----------------
// C[m][n] = f( alpha * sum_k A[m][k]*B[n][k] )
// MODE 0: + bias[n], column segments of Nout select C0/C1/C2 (fused QKV)
// MODE 1: exp() in epilogue, row sums atomically added into Z
// MODE 2: multiply by 1/Z[row]
template <int MODE, typename OutT>
__global__ void __launch_bounds__(THREADS, 1)
gemm_tn(const __half* __restrict__ A, const __half* __restrict__ B,
        const float* b0p, const float* b1p, const float* b2p,
        OutT* C0, OutT* C1, OutT* C2, float* __restrict__ Z,
        int Nout, int K, long long strA, long long strB, long long strC, float alpha) {
    extern __shared__ __align__(128) char smem[];
    const uint32_t sb = smem_u32(smem);

    A += (long long)blockIdx.z * strA;
    B += (long long)blockIdx.z * strB;
    if (MODE != 0 && Z) Z += (long long)blockIdx.z * (strC / Nout);

    const int tid  = threadIdx.x;
    const int lane = tid & 31;
    const int warp = tid >> 5;        // 8 warps: 2 (M) x 4 (N)
    const int wr   = warp & 1;
    const int wc   = warp >> 1;
    const int grp  = lane >> 2;
    const int tig  = lane & 3;

    const int m0 = blockIdx.x * 128;   // m on x: consecutive CTAs share B tile
    const int n0 = blockIdx.y * 256;

    const int seg = (MODE == 0) ? (n0 / Nout) : 0;
    const int nc0 = n0 - seg * Nout;
    OutT* C = (seg == 0) ? C0 : (seg == 1) ? C1 : C2;
    const float* bias = (seg == 0) ? b0p : (seg == 1) ? b1p : b2p;
    C += (long long)blockIdx.z * strC;

    float acc[4][8][4];
#pragma unroll
    for (int i = 0; i < 4; i++)
#pragma unroll
        for (int j = 0; j < 8; j++)
#pragma unroll
            for (int v = 0; v < 4; v++) acc[i][j][v] = 0.0f;

    auto aS = [&](int s) -> uint32_t { return sb + s * A_STG; };
    auto bS = [&](int s) -> uint32_t { return sb + OFF_B + s * B_STG; };

    auto loadA = [&](int s, int kt) {
#pragma unroll
        for (int i = 0; i < 4; i++) {
            int c = i * THREADS + tid;        // 1024 16B chunks
            int row = c >> 3, ch = c & 7;
            cp16s(aS(s) + SWZ(row * 128 + ch * 16),
                  A + (size_t)(m0 + row) * K + kt * 64 + ch * 8);
        }
    };
    auto loadB = [&](int s, int kt) {
#pragma unroll
        for (int i = 0; i < 8; i++) {
            int c = i * THREADS + tid;        // 2048 16B chunks
            int row = c >> 3, ch = c & 7;
            cp16s(bS(s) + SWZ(row * 128 + ch * 16),
                  B + (size_t)(n0 + row) * K + kt * 64 + ch * 8);
        }
    };

    const int ktiles = K / 64;
    loadA(0, 0); loadB(0, 0); cp_commit();
    loadA(1, 1); loadB(1, 1); cp_commit();

    // per-thread ldmatrix lane offsets
    const int a_row = lane & 15;                      // row within 16
    const int a_ko  = (lane >> 4) << 4;               // 0 / 16 bytes
    const int b_row = (lane & 7) + ((lane >> 4) << 3);// row within 16
    const int b_ko  = ((lane >> 3) & 1) << 4;         // 0 / 16 bytes
    const int rm = wr * 64;
    const int nb = wc * 64;

    for (int kt = 0; kt < ktiles; kt++) {
        cp_wait<1>();
        __syncthreads();   // single barrier: orders stage reuse AND data ready

        if (kt + 2 < ktiles) {
            int ns = (kt + 2) % 3;
            loadA(ns, kt + 2);
            loadB(ns, kt + 2);
        }
        cp_commit();

        const uint32_t cA = aS(kt % 3);
        const uint32_t cB = bS(kt % 3);

#pragma unroll
        for (int st = 0; st < 4; st++) {
            const int kkb = st * 32;                  // byte offset of k16 step
            uint32_t af[4][4];
#pragma unroll
            for (int mt = 0; mt < 4; mt++)
                ldsm4(af[mt], cA + SWZ((rm + mt * 16 + a_row) * 128 + kkb + a_ko));
            uint32_t bf[8][2];
#pragma unroll
            for (int j = 0; j < 4; j++) {
                uint32_t t[4];
                ldsm4(t, cB + SWZ((nb + j * 16 + b_row) * 128 + kkb + b_ko));
                bf[2 * j][0] = t[0]; bf[2 * j][1] = t[1];
                bf[2 * j + 1][0] = t[2]; bf[2 * j + 1][1] = t[3];
            }
#pragma unroll
            for (int mt = 0; mt < 4; mt++)
#pragma unroll
                for (int nt = 0; nt < 8; nt++) mma16816(acc[mt][nt], af[mt], bf[nt]);
        }
        // no trailing barrier: next iteration's top barrier protects stage reuse
    }

    // ---------------- epilogue ----------------
    if (MODE == 0) {
#pragma unroll
        for (int mt = 0; mt < 4; mt++) {
#pragma unroll
            for (int nt = 0; nt < 8; nt++) {
                int row = m0 + wr * 64 + mt * 16 + grp;
                int col = nc0 + wc * 64 + nt * 8 + 2 * tig;
                float bb0 = bias[col], bb1 = bias[col + 1];
                float* c = acc[mt][nt];
                store2(C, (size_t)row * Nout + col,       c[0] + bb0, c[1] + bb1);
                store2(C, (size_t)(row + 8) * Nout + col, c[2] + bb0, c[3] + bb1);
            }
        }
    } else if (MODE == 1) {
        const float e2 = alpha * 1.44269504f;      // exp(x*alpha) = exp2(x*alpha*log2e)
#pragma unroll
        for (int mt = 0; mt < 4; mt++) {
            int row = m0 + wr * 64 + mt * 16 + grp;
            float z0 = 0.0f, z1 = 0.0f;
#pragma unroll
            for (int nt = 0; nt < 8; nt++) {
                int col = n0 + wc * 64 + nt * 8 + 2 * tig;
                float* c = acc[mt][nt];
                float p0 = exp2f(c[0] * e2), p1 = exp2f(c[1] * e2);
                float p2 = exp2f(c[2] * e2), p3 = exp2f(c[3] * e2);
                store2(C, (size_t)row * Nout + col,       p0, p1);
                store2(C, (size_t)(row + 8) * Nout + col, p2, p3);
                z0 += p0 + p1; z1 += p2 + p3;
            }
            z0 += __shfl_xor_sync(0xffffffffu, z0, 1);
            z0 += __shfl_xor_sync(0xffffffffu, z0, 2);
            z1 += __shfl_xor_sync(0xffffffffu, z1, 1);
            z1 += __shfl_xor_sync(0xffffffffu, z1, 2);
            if (tig == 0) {
                atomicAdd(Z + row,     z0);
                atomicAdd(Z + row + 8, z1);
            }
        }
    } else {   // MODE 2
#pragma unroll
        for (int mt = 0; mt < 4; mt++) {
            int row = m0 + wr * 64 + mt * 16 + grp;
            float iz0 = 1.0f / Z[row];
            float iz8 = 1.0f / Z[row + 8];
#pragma unroll
            for (int nt = 0; nt < 8; nt++) {
                int col = n0 + wc * 64 + nt * 8 + 2 * tig;
                float* c = acc[mt][nt];
                store2(C, (size_t)row * Nout + col,       c[0] * iz0, c[1] * iz0);
                store2(C, (size_t)(row + 8) * Nout + col, c[2] * iz8, c[3] * iz8);
            }
        }
    }
}

// ---------------- converts / transposes ----------------
__global__ void f2h_kernel(const float* __restrict__ in, __half* __restrict__ out, size_t n) {
    size_t i = ((size_t)blockIdx.x * blockDim.x + threadIdx.x) * 4;
    if (i < n) {
        float4 v = *(const float4*)(in + i);
        __half2* o = (__half2*)(out + i);
        o[0] = __floats2half2_rn(v.x, v.y);
        o[1] = __floats2half2_rn(v.z, v.w);
    }
}

__global__ void zeroZ_kernel(float* __restrict__ Z) {
    Z[blockIdx.x * 256 + threadIdx.x] = 0.0f;
}

__global__ void tr_f2h(const float* __restrict__ in, __half* __restrict__ out, int R, int C) {
    __shared__ float t[32][33];
    int c0 = blockIdx.x * 32, r0 = blockIdx.y * 32;
#pragma unroll
    for (int i = threadIdx.y; i < 32; i += 8)
        t[i][threadIdx.x] = in[(size_t)(r0 + i) * C + c0 + threadIdx.x];
    __syncthreads();
#pragma unroll
    for (int i = threadIdx.y; i < 32; i += 8)
        out[(size_t)(c0 + i) * R + r0 + threadIdx.x] = __float2half(t[threadIdx.x][i]);
}

__global__ void tr_h(const __half* __restrict__ in, __half* __restrict__ out, int R, int C) {
    in  += (size_t)blockIdx.z * R * C;
    out += (size_t)blockIdx.z * R * C;
    __shared__ __half t[32][33];
    int c0 = blockIdx.x * 32, r0 = blockIdx.y * 32;
#pragma unroll
    for (int i = threadIdx.y; i < 32; i += 8)
        t[i][threadIdx.x] = in[(size_t)(r0 + i) * C + c0 + threadIdx.x];
    __syncthreads();
#pragma unroll
    for (int i = threadIdx.y; i < 32; i += 8)
        out[(size_t)(c0 + i) * R + r0 + threadIdx.x] = t[threadIdx.x][i];
}

// ---------------- launch ----------------
extern "C" void kernel_launch(void* const* d_in, const int* in_sizes, int n_in,
                              void* d_out, int out_size) {
    const float* X  = (const float*)d_in[0];
    const float* Wq = (const float*)d_in[1];
    const float* Wk = (const float*)d_in[2];
    const float* Wv = (const float*)d_in[3];
    const float* bq = (const float*)d_in[4];
    const float* bk = (const float*)d_in[5];
    const float* bv = (const float*)d_in[6];
    float* O = (float*)d_out;

    __half *Xh, *Wt, *Qh, *Kh, *Vh, *Vt, *S;
    float* Zp;
    cudaGetSymbolAddress((void**)&Xh, g_Xh);
    cudaGetSymbolAddress((void**)&Wt, g_Wt);
    cudaGetSymbolAddress((void**)&Qh, g_Qh);
    cudaGetSymbolAddress((void**)&Kh, g_Kh);
    cudaGetSymbolAddress((void**)&Vh, g_Vh);
    cudaGetSymbolAddress((void**)&Vt, g_Vt);
    cudaGetSymbolAddress((void**)&S,  g_S);
    cudaGetSymbolAddress((void**)&Zp, g_Z);

    const int D = 1024, N = 4096;

    static int attr_done = 0;
    if (!attr_done) {
        cudaFuncSetAttribute((const void*)gemm_tn<0, __half>, cudaFuncAttributeMaxDynamicSharedMemorySize, SMEM_TOTAL);
        cudaFuncSetAttribute((const void*)gemm_tn<1, __half>, cudaFuncAttributeMaxDynamicSharedMemorySize, SMEM_TOTAL);
        cudaFuncSetAttribute((const void*)gemm_tn<2, float>,  cudaFuncAttributeMaxDynamicSharedMemorySize, SMEM_TOTAL);
        attr_done = 1;
    }

    // 0) converts + Z zero
    {
        size_t n = (size_t)4 * N * D;
        f2h_kernel<<<(unsigned)(n / 4 / 256), 256>>>(X, Xh, n);
        dim3 b(32, 8), g(D / 32, D / 32);
        tr_f2h<<<g, b>>>(Wq, Wt + 0ull * D * D, D, D);
        tr_f2h<<<g, b>>>(Wk, Wt + 1ull * D * D, D, D);
        tr_f2h<<<g, b>>>(Wv, Wt + 2ull * D * D, D, D);
        zeroZ_kernel<<<4 * N / 256, 256>>>(Zp);
    }

    // 1) fused QKV: [16384,1024] x [3072,1024]^T, split into Q/K/V
    {
        dim3 g(4 * N / 128, 3 * D / 256, 1);
        gemm_tn<0, __half><<<g, THREADS, SMEM_TOTAL>>>(
            Xh, Wt, bq, bk, bv, Qh, Kh, Vh, nullptr, D, D, 0, 0, 0, 1.0f);
    }

    // 2) V transpose per batch
    {
        dim3 b(32, 8), g(D / 32, N / 32, 4);
        tr_h<<<g, b>>>(Vh, Vt, N, D);
    }

    // 3) P = exp(Q K^T / 32), Z row sums (fp16 out)
    {
        dim3 g(N / 128, N / 256, 4);
        gemm_tn<1, __half><<<g, THREADS, SMEM_TOTAL>>>(
            Qh, Kh, nullptr, nullptr, nullptr, S, nullptr, nullptr, Zp,
            N, D, (long long)N * D, (long long)N * D, (long long)N * N, 0.03125f);
    }

    // 4) O = (P Vt^T) / Z (fp32 out)
    {
        dim3 g(N / 128, D / 256, 4);
        gemm_tn<2, float><<<g, THREADS, SMEM_TOTAL>>>(
            S, Vt, nullptr, nullptr, nullptr, O, nullptr, nullptr, Zp,
            D, N, (long long)N * N, (long long)N * D, (long long)N * D, 1.0f);
    }
}

// round 8
// speedup vs baseline: 3.9162x; 1.0324x over previous
#include <cuda_runtime.h>
#include <cuda_fp16.h>
#include <cstdint>
#include <math.h>

// ---------------------------------------------------------------------------
// SelfAttention B=4, N=4096, d=1024, fp32 in/out, rel_err < 1e-3.
// mma.sync fp16 path, softmax fused into GEMM epilogues.
//   0) X -> fp16; Wq/Wk/Wv -> transposed fp16 (one batched launch)
//   1) fused QKV = Xh * Wcat^T + b     (MODE0, BN=256, fp16 out)
//   2) Vh -> Vt transpose
//   3) P = exp(Q K^T / 32), Z row sums (MODE1, BN=256, fp16 out)
//   4) O = (P Vt^T) / Z                (MODE2, BN=128, 2 CTA/SM, fp32 out)
// GEMM: BM=128, BN templated {256,128}, BK=64, SW128 smem, cp.async 3-stage,
// ldmatrix.x4, one barrier per k-tile.
// Launch order puts the S-GEMM at index 5 so ncu -s5 captures it.
// ---------------------------------------------------------------------------

#define THREADS 256
#define A_STG 16384                   // 128 rows * 128B

#define SWZ(o) ((o) ^ (((o) >> 3) & 0x70))

// scratch
__device__ __half g_Xh[(size_t)4 * 4096 * 1024];
__device__ __half g_Wt[3ull * 1024 * 1024];        // [3072][1024] (Q,K,V concat)
__device__ __half g_Qh[(size_t)4 * 4096 * 1024];
__device__ __half g_Kh[(size_t)4 * 4096 * 1024];
__device__ __half g_Vh[(size_t)4 * 4096 * 1024];
__device__ __half g_Vt[(size_t)4 * 4096 * 1024];
__device__ __half g_S [(size_t)4 * 4096 * 4096];   // un-normalized exp(S)
__device__ float  g_Z [4 * 4096];                  // row sums of exp(S)

// ---------------- PTX helpers ----------------
__device__ __forceinline__ uint32_t smem_u32(const void* p) {
    uint32_t a;
    asm("{ .reg .u64 t; cvta.to.shared.u64 t, %1; cvt.u32.u64 %0, t; }" : "=r"(a) : "l"(p));
    return a;
}
__device__ __forceinline__ void cp16s(uint32_t s, const void* g) {
    asm volatile("cp.async.cg.shared.global [%0], [%1], 16;\n" :: "r"(s), "l"(g));
}
__device__ __forceinline__ void cp_commit() { asm volatile("cp.async.commit_group;\n"); }
template <int N> __device__ __forceinline__ void cp_wait() {
    asm volatile("cp.async.wait_group %0;\n" :: "n"(N));
}
__device__ __forceinline__ void ldsm4(uint32_t* r, uint32_t addr) {
    asm volatile("ldmatrix.sync.aligned.m8n8.x4.shared.b16 {%0,%1,%2,%3}, [%4];"
        : "=r"(r[0]), "=r"(r[1]), "=r"(r[2]), "=r"(r[3]) : "r"(addr));
}
__device__ __forceinline__ void mma16816(float c[4], const uint32_t a[4], const uint32_t b[2]) {
    asm volatile(
        "mma.sync.aligned.m16n8k16.row.col.f32.f16.f16.f32 "
        "{%0,%1,%2,%3},{%4,%5,%6,%7},{%8,%9},{%0,%1,%2,%3};"
        : "+f"(c[0]), "+f"(c[1]), "+f"(c[2]), "+f"(c[3])
        : "r"(a[0]), "r"(a[1]), "r"(a[2]), "r"(a[3]), "r"(b[0]), "r"(b[1]));
}

__device__ __forceinline__ void store2(__half* C, size_t idx, float v0, float v1) {
    *(__half2*)(C + idx) = __floats2half2_rn(v0, v1);
}
__device__ __forceinline__ void store2(float* C, size_t idx, float v0, float v1) {
    float2 t; t.x = v0; t.y = v1;
    *(float2*)(C + idx) = t;
}

// ---------------- TN GEMM ----------------
// C[m][n] = f( alpha * sum_k A[m][k]*B[n][k] )
// MODE 0: + bias[n], column segments of Nout select C0/C1/C2 (fused QKV)
// MODE 1: exp() in epilogue, row sums atomically added into Z
// MODE 2: multiply by 1/Z[row]
// BN_: 256 (1 CTA/SM) or 128 (2 CTA/SM).
template <int MODE, int BN_, typename OutT>
__global__ void __launch_bounds__(THREADS, (BN_ == 128) ? 2 : 1)
gemm_tn(const __half* __restrict__ A, const __half* __restrict__ B,
        const float* b0p, const float* b1p, const float* b2p,
        OutT* C0, OutT* C1, OutT* C2, float* __restrict__ Z,
        int Nout, int K, long long strA, long long strB, long long strC, float alpha) {
    constexpr int B_STG = BN_ * 128;
    constexpr int OFF_B = 3 * A_STG;
    constexpr int NT = BN_ / 32;          // n-tiles per warp (8 or 4)
    constexpr int WN = BN_ / 4;           // warp n extent (64 or 32)

    extern __shared__ __align__(128) char smem[];
    const uint32_t sb = smem_u32(smem);

    A += (long long)blockIdx.z * strA;
    B += (long long)blockIdx.z * strB;
    if (MODE != 0 && Z) Z += (long long)blockIdx.z * (strC / Nout);

    const int tid  = threadIdx.x;
    const int lane = tid & 31;
    const int warp = tid >> 5;        // 8 warps: 2 (M) x 4 (N)
    const int wr   = warp & 1;
    const int wc   = warp >> 1;
    const int grp  = lane >> 2;
    const int tig  = lane & 3;

    const int m0 = blockIdx.x * 128;   // m on x: consecutive CTAs share B tile
    const int n0 = blockIdx.y * BN_;

    const int seg = (MODE == 0) ? (n0 / Nout) : 0;
    const int nc0 = n0 - seg * Nout;
    OutT* C = (seg == 0) ? C0 : (seg == 1) ? C1 : C2;
    const float* bias = (seg == 0) ? b0p : (seg == 1) ? b1p : b2p;
    C += (long long)blockIdx.z * strC;

    float acc[4][NT][4];
#pragma unroll
    for (int i = 0; i < 4; i++)
#pragma unroll
        for (int j = 0; j < NT; j++)
#pragma unroll
            for (int v = 0; v < 4; v++) acc[i][j][v] = 0.0f;

    auto aS = [&](int s) -> uint32_t { return sb + s * A_STG; };
    auto bS = [&](int s) -> uint32_t { return sb + OFF_B + s * B_STG; };

    auto loadA = [&](int s, int kt) {
#pragma unroll
        for (int i = 0; i < 4; i++) {
            int c = i * THREADS + tid;        // 1024 16B chunks
            int row = c >> 3, ch = c & 7;
            cp16s(aS(s) + SWZ(row * 128 + ch * 16),
                  A + (size_t)(m0 + row) * K + kt * 64 + ch * 8);
        }
    };
    auto loadB = [&](int s, int kt) {
#pragma unroll
        for (int i = 0; i < BN_ / 32; i++) {  // BN_*8 chunks / 256 threads
            int c = i * THREADS + tid;
            int row = c >> 3, ch = c & 7;
            cp16s(bS(s) + SWZ(row * 128 + ch * 16),
                  B + (size_t)(n0 + row) * K + kt * 64 + ch * 8);
        }
    };

    const int ktiles = K / 64;
    loadA(0, 0); loadB(0, 0); cp_commit();
    loadA(1, 1); loadB(1, 1); cp_commit();

    // per-thread ldmatrix lane offsets
    const int a_row = lane & 15;                      // row within 16
    const int a_ko  = (lane >> 4) << 4;               // 0 / 16 bytes
    const int b_row = (lane & 7) + ((lane >> 4) << 3);// row within 16
    const int b_ko  = ((lane >> 3) & 1) << 4;         // 0 / 16 bytes
    const int rm = wr * 64;
    const int nb = wc * WN;

    for (int kt = 0; kt < ktiles; kt++) {
        cp_wait<1>();
        __syncthreads();   // single barrier: orders stage reuse AND data ready

        if (kt + 2 < ktiles) {
            int ns = (kt + 2) % 3;
            loadA(ns, kt + 2);
            loadB(ns, kt + 2);
        }
        cp_commit();

        const uint32_t cA = aS(kt % 3);
        const uint32_t cB = bS(kt % 3);

#pragma unroll
        for (int st = 0; st < 4; st++) {
            const int kkb = st * 32;                  // byte offset of k16 step
            uint32_t af[4][4];
#pragma unroll
            for (int mt = 0; mt < 4; mt++)
                ldsm4(af[mt], cA + SWZ((rm + mt * 16 + a_row) * 128 + kkb + a_ko));
            uint32_t bf[NT][2];
#pragma unroll
            for (int j = 0; j < NT / 2; j++) {
                uint32_t t[4];
                ldsm4(t, cB + SWZ((nb + j * 16 + b_row) * 128 + kkb + b_ko));
                bf[2 * j][0] = t[0]; bf[2 * j][1] = t[1];
                bf[2 * j + 1][0] = t[2]; bf[2 * j + 1][1] = t[3];
            }
#pragma unroll
            for (int mt = 0; mt < 4; mt++)
#pragma unroll
                for (int nt = 0; nt < NT; nt++) mma16816(acc[mt][nt], af[mt], bf[nt]);
        }
        // no trailing barrier: next iteration's top barrier protects stage reuse
    }

    // ---------------- epilogue ----------------
    if (MODE == 0) {
#pragma unroll
        for (int mt = 0; mt < 4; mt++) {
#pragma unroll
            for (int nt = 0; nt < NT; nt++) {
                int row = m0 + wr * 64 + mt * 16 + grp;
                int col = nc0 + wc * WN + nt * 8 + 2 * tig;
                float bb0 = bias[col], bb1 = bias[col + 1];
                float* c = acc[mt][nt];
                store2(C, (size_t)row * Nout + col,       c[0] + bb0, c[1] + bb1);
                store2(C, (size_t)(row + 8) * Nout + col, c[2] + bb0, c[3] + bb1);
            }
        }
    } else if (MODE == 1) {
        const float e2 = alpha * 1.44269504f;      // exp(x*alpha) = exp2(x*alpha*log2e)
#pragma unroll
        for (int mt = 0; mt < 4; mt++) {
            int row = m0 + wr * 64 + mt * 16 + grp;
            float z0 = 0.0f, z1 = 0.0f;
#pragma unroll
            for (int nt = 0; nt < NT; nt++) {
                int col = n0 + wc * WN + nt * 8 + 2 * tig;
                float* c = acc[mt][nt];
                float p0 = exp2f(c[0] * e2), p1 = exp2f(c[1] * e2);
                float p2 = exp2f(c[2] * e2), p3 = exp2f(c[3] * e2);
                store2(C, (size_t)row * Nout + col,       p0, p1);
                store2(C, (size_t)(row + 8) * Nout + col, p2, p3);
                z0 += p0 + p1; z1 += p2 + p3;
            }
            z0 += __shfl_xor_sync(0xffffffffu, z0, 1);
            z0 += __shfl_xor_sync(0xffffffffu, z0, 2);
            z1 += __shfl_xor_sync(0xffffffffu, z1, 1);
            z1 += __shfl_xor_sync(0xffffffffu, z1, 2);
            if (tig == 0) {
                atomicAdd(Z + row,     z0);
                atomicAdd(Z + row + 8, z1);
            }
        }
    } else {   // MODE 2
#pragma unroll
        for (int mt = 0; mt < 4; mt++) {
            int row = m0 + wr * 64 + mt * 16 + grp;
            float iz0 = 1.0f / Z[row];
            float iz8 = 1.0f / Z[row + 8];
#pragma unroll
            for (int nt = 0; nt < NT; nt++) {
                int col = n0 + wc * WN + nt * 8 + 2 * tig;
                float* c = acc[mt][nt];
                store2(C, (size_t)row * Nout + col,       c[0] * iz0, c[1] * iz0);
                store2(C, (size_t)(row + 8) * Nout + col, c[2] * iz8, c[3] * iz8);
            }
        }
    }
}

// ---------------- converts / transposes ----------------
__global__ void f2h_kernel(const float* __restrict__ in, __half* __restrict__ out, size_t n) {
    size_t i = ((size_t)blockIdx.x * blockDim.x + threadIdx.x) * 4;
    if (i < n) {
        float4 v = *(const float4*)(in + i);
        __half2* o = (__half2*)(out + i);
        o[0] = __floats2half2_rn(v.x, v.y);
        o[1] = __floats2half2_rn(v.z, v.w);
    }
}

__global__ void zeroZ_kernel(float* __restrict__ Z) {
    Z[blockIdx.x * 256 + threadIdx.x] = 0.0f;
}

// batched: z selects which W (fp32 [R][C]) -> out + z*R*C (fp16 [C][R])
__global__ void trW_f2h(const float* __restrict__ W0, const float* __restrict__ W1,
                        const float* __restrict__ W2, __half* __restrict__ out,
                        int R, int C) {
    const float* in = (blockIdx.z == 0) ? W0 : (blockIdx.z == 1) ? W1 : W2;
    out += (size_t)blockIdx.z * R * C;
    __shared__ float t[32][33];
    int c0 = blockIdx.x * 32, r0 = blockIdx.y * 32;
#pragma unroll
    for (int i = threadIdx.y; i < 32; i += 8)
        t[i][threadIdx.x] = in[(size_t)(r0 + i) * C + c0 + threadIdx.x];
    __syncthreads();
#pragma unroll
    for (int i = threadIdx.y; i < 32; i += 8)
        out[(size_t)(c0 + i) * R + r0 + threadIdx.x] = __float2half(t[threadIdx.x][i]);
}

__global__ void tr_h(const __half* __restrict__ in, __half* __restrict__ out, int R, int C) {
    in  += (size_t)blockIdx.z * R * C;
    out += (size_t)blockIdx.z * R * C;
    __shared__ __half t[32][33];
    int c0 = blockIdx.x * 32, r0 = blockIdx.y * 32;
#pragma unroll
    for (int i = threadIdx.y; i < 32; i += 8)
        t[i][threadIdx.x] = in[(size_t)(r0 + i) * C + c0 + threadIdx.x];
    __syncthreads();
#pragma unroll
    for (int i = threadIdx.y; i < 32; i += 8)
        out[(size_t)(c0 + i) * R + r0 + threadIdx.x] = t[threadIdx.x][i];
}

// ---------------- launch ----------------
extern "C" void kernel_launch(void* const* d_in, const int* in_sizes, int n_in,
                              void* d_out, int out_size) {
    const float* X  = (const float*)d_in[0];
    const float* Wq = (const float*)d_in[1];
    const float* Wk = (const float*)d_in[2];
    const float* Wv = (const float*)d_in[3];
    const float* bq = (const float*)d_in[4];
    const float* bk = (const float*)d_in[5];
    const float* bv = (const float*)d_in[6];
    float* O = (float*)d_out;

    __half *Xh, *Wt, *Qh, *Kh, *Vh, *Vt, *S;
    float* Zp;
    cudaGetSymbolAddress((void**)&Xh, g_Xh);
    cudaGetSymbolAddress((void**)&Wt, g_Wt);
    cudaGetSymbolAddress((void**)&Qh, g_Qh);
    cudaGetSymbolAddress((void**)&Kh, g_Kh);
    cudaGetSymbolAddress((void**)&Vh, g_Vh);
    cudaGetSymbolAddress((void**)&Vt, g_Vt);
    cudaGetSymbolAddress((void**)&S,  g_S);
    cudaGetSymbolAddress((void**)&Zp, g_Z);

    const int D = 1024, N = 4096;
    const int SMEM_256 = 3 * (A_STG + 256 * 128);   // 147456
    const int SMEM_128 = 3 * (A_STG + 128 * 128);   // 98304

    static int attr_done = 0;
    if (!attr_done) {
        cudaFuncSetAttribute((const void*)gemm_tn<0, 256, __half>, cudaFuncAttributeMaxDynamicSharedMemorySize, SMEM_256);
        cudaFuncSetAttribute((const void*)gemm_tn<1, 256, __half>, cudaFuncAttributeMaxDynamicSharedMemorySize, SMEM_256);
        cudaFuncSetAttribute((const void*)gemm_tn<2, 128, float>,  cudaFuncAttributeMaxDynamicSharedMemorySize, SMEM_128);
        attr_done = 1;
    }

    // launch index:                                            idx
    {
        size_t n = (size_t)4 * N * D;
        f2h_kernel<<<(unsigned)(n / 4 / 256), 256>>>(X, Xh, n);          // 0
        dim3 b(32, 8), g(D / 32, D / 32, 3);
        trW_f2h<<<g, b>>>(Wq, Wk, Wv, Wt, D, D);                         // 1
        zeroZ_kernel<<<4 * N / 256, 256>>>(Zp);                          // 2
    }

    // 1) fused QKV                                                      // 3
    {
        dim3 g(4 * N / 128, 3 * D / 256, 1);
        gemm_tn<0, 256, __half><<<g, THREADS, SMEM_256>>>(
            Xh, Wt, bq, bk, bv, Qh, Kh, Vh, nullptr, D, D, 0, 0, 0, 1.0f);
    }

    // 2) V transpose per batch                                          // 4
    {
        dim3 b(32, 8), g(D / 32, N / 32, 4);
        tr_h<<<g, b>>>(Vh, Vt, N, D);
    }

    // 3) P = exp(Q K^T / 32), Z row sums                                // 5 (ncu -s5)
    {
        dim3 g(N / 128, N / 256, 4);
        gemm_tn<1, 256, __half><<<g, THREADS, SMEM_256>>>(
            Qh, Kh, nullptr, nullptr, nullptr, S, nullptr, nullptr, Zp,
            N, D, (long long)N * D, (long long)N * D, (long long)N * N, 0.03125f);
    }

    // 4) O = (P Vt^T) / Z  (BN=128, 2 CTA/SM)                           // 6
    {
        dim3 g(N / 128, D / 128, 4);
        gemm_tn<2, 128, float><<<g, THREADS, SMEM_128>>>(
            S, Vt, nullptr, nullptr, nullptr, O, nullptr, nullptr, Zp,
            D, N, (long long)N * N, (long long)N * D, (long long)N * D, 1.0f);
    }
}

// round 9
// speedup vs baseline: 4.0344x; 1.0302x over previous
#include <cuda_runtime.h>
#include <cuda_fp16.h>
#include <cstdint>
#include <math.h>

// ---------------------------------------------------------------------------
// SelfAttention B=4, N=4096, d=1024, fp32 in/out, rel_err < 1e-3.
// mma.sync fp16 path, softmax fused into GEMM epilogues.
// ALL GEMMs: BM=128 BN=128, 2 CTAs/SM (regs<=168, no spill), BK=64,
// SW128 smem, cp.async 3-stage, ldmatrix.x4, one barrier per k-tile.
//   0) X -> fp16; Wq/Wk/Wv -> transposed fp16 (one batched launch)
//   1) fused QKV = Xh * Wcat^T + b     (MODE0, fp16 out)
//   2) Vh -> Vt transpose
//   3) P = exp(Q K^T / 32), Z row sums (MODE1, fp16 out)
//   4) O = (P Vt^T) / Z                (MODE2, fp32 out)
// ---------------------------------------------------------------------------

#define THREADS 256
#define A_STG 16384                   // 128 rows * 128B

#define SWZ(o) ((o) ^ (((o) >> 3) & 0x70))

// scratch
__device__ __half g_Xh[(size_t)4 * 4096 * 1024];
__device__ __half g_Wt[3ull * 1024 * 1024];        // [3072][1024] (Q,K,V concat)
__device__ __half g_Qh[(size_t)4 * 4096 * 1024];
__device__ __half g_Kh[(size_t)4 * 4096 * 1024];
__device__ __half g_Vh[(size_t)4 * 4096 * 1024];
__device__ __half g_Vt[(size_t)4 * 4096 * 1024];
__device__ __half g_S [(size_t)4 * 4096 * 4096];   // un-normalized exp(S)
__device__ float  g_Z [4 * 4096];                  // row sums of exp(S)

// ---------------- PTX helpers ----------------
__device__ __forceinline__ uint32_t smem_u32(const void* p) {
    uint32_t a;
    asm("{ .reg .u64 t; cvta.to.shared.u64 t, %1; cvt.u32.u64 %0, t; }" : "=r"(a) : "l"(p));
    return a;
}
__device__ __forceinline__ void cp16s(uint32_t s, const void* g) {
    asm volatile("cp.async.cg.shared.global [%0], [%1], 16;\n" :: "r"(s), "l"(g));
}
__device__ __forceinline__ void cp_commit() { asm volatile("cp.async.commit_group;\n"); }
template <int N> __device__ __forceinline__ void cp_wait() {
    asm volatile("cp.async.wait_group %0;\n" :: "n"(N));
}
__device__ __forceinline__ void ldsm4(uint32_t* r, uint32_t addr) {
    asm volatile("ldmatrix.sync.aligned.m8n8.x4.shared.b16 {%0,%1,%2,%3}, [%4];"
        : "=r"(r[0]), "=r"(r[1]), "=r"(r[2]), "=r"(r[3]) : "r"(addr));
}
__device__ __forceinline__ void mma16816(float c[4], const uint32_t a[4], const uint32_t b[2]) {
    asm volatile(
        "mma.sync.aligned.m16n8k16.row.col.f32.f16.f16.f32 "
        "{%0,%1,%2,%3},{%4,%5,%6,%7},{%8,%9},{%0,%1,%2,%3};"
        : "+f"(c[0]), "+f"(c[1]), "+f"(c[2]), "+f"(c[3])
        : "r"(a[0]), "r"(a[1]), "r"(a[2]), "r"(a[3]), "r"(b[0]), "r"(b[1]));
}

__device__ __forceinline__ void store2(__half* C, size_t idx, float v0, float v1) {
    *(__half2*)(C + idx) = __floats2half2_rn(v0, v1);
}
__device__ __forceinline__ void store2(float* C, size_t idx, float v0, float v1) {
    float2 t; t.x = v0; t.y = v1;
    *(float2*)(C + idx) = t;
}

// ---------------- TN GEMM ----------------
// C[m][n] = f( alpha * sum_k A[m][k]*B[n][k] )
// MODE 0: + bias[n], column segments of Nout select C0/C1/C2 (fused QKV)
// MODE 1: exp() in epilogue, row sums atomically added into Z
// MODE 2: multiply by 1/Z[row]
// BM=128, BN=128, 8 warps (2M x 4N), warp tile 64x32, 2 CTAs/SM.
template <int MODE, typename OutT>
__global__ void __launch_bounds__(THREADS, 2)
gemm_tn(const __half* __restrict__ A, const __half* __restrict__ B,
        const float* b0p, const float* b1p, const float* b2p,
        OutT* C0, OutT* C1, OutT* C2, float* __restrict__ Z,
        int Nout, int K, long long strA, long long strB, long long strC, float alpha) {
    constexpr int BN_ = 128;
    constexpr int B_STG = BN_ * 128;
    constexpr int OFF_B = 3 * A_STG;
    constexpr int NT = BN_ / 32;          // 4 n-tiles per warp
    constexpr int WN = BN_ / 4;           // 32 warp n extent

    extern __shared__ __align__(128) char smem[];
    const uint32_t sb = smem_u32(smem);

    A += (long long)blockIdx.z * strA;
    B += (long long)blockIdx.z * strB;
    if (MODE != 0 && Z) Z += (long long)blockIdx.z * (strC / Nout);

    const int tid  = threadIdx.x;
    const int lane = tid & 31;
    const int warp = tid >> 5;        // 8 warps: 2 (M) x 4 (N)
    const int wr   = warp & 1;
    const int wc   = warp >> 1;
    const int grp  = lane >> 2;
    const int tig  = lane & 3;

    const int m0 = blockIdx.x * 128;   // m on x: consecutive CTAs share B tile
    const int n0 = blockIdx.y * BN_;

    const int seg = (MODE == 0) ? (n0 / Nout) : 0;
    const int nc0 = n0 - seg * Nout;
    OutT* C = (seg == 0) ? C0 : (seg == 1) ? C1 : C2;
    const float* bias = (seg == 0) ? b0p : (seg == 1) ? b1p : b2p;
    C += (long long)blockIdx.z * strC;

    float acc[4][NT][4];
#pragma unroll
    for (int i = 0; i < 4; i++)
#pragma unroll
        for (int j = 0; j < NT; j++)
#pragma unroll
            for (int v = 0; v < 4; v++) acc[i][j][v] = 0.0f;

    auto aS = [&](int s) -> uint32_t { return sb + s * A_STG; };
    auto bS = [&](int s) -> uint32_t { return sb + OFF_B + s * B_STG; };

    auto loadA = [&](int s, int kt) {
#pragma unroll
        for (int i = 0; i < 4; i++) {
            int c = i * THREADS + tid;        // 1024 16B chunks
            int row = c >> 3, ch = c & 7;
            cp16s(aS(s) + SWZ(row * 128 + ch * 16),
                  A + (size_t)(m0 + row) * K + kt * 64 + ch * 8);
        }
    };
    auto loadB = [&](int s, int kt) {
#pragma unroll
        for (int i = 0; i < 4; i++) {         // 1024 16B chunks
            int c = i * THREADS + tid;
            int row = c >> 3, ch = c & 7;
            cp16s(bS(s) + SWZ(row * 128 + ch * 16),
                  B + (size_t)(n0 + row) * K + kt * 64 + ch * 8);
        }
    };

    const int ktiles = K / 64;
    loadA(0, 0); loadB(0, 0); cp_commit();
    loadA(1, 1); loadB(1, 1); cp_commit();

    // per-thread ldmatrix lane offsets
    const int a_row = lane & 15;                      // row within 16
    const int a_ko  = (lane >> 4) << 4;               // 0 / 16 bytes
    const int b_row = (lane & 7) + ((lane >> 4) << 3);// row within 16
    const int b_ko  = ((lane >> 3) & 1) << 4;         // 0 / 16 bytes
    const int rm = wr * 64;
    const int nb = wc * WN;

    for (int kt = 0; kt < ktiles; kt++) {
        cp_wait<1>();
        __syncthreads();   // single barrier: orders stage reuse AND data ready

        if (kt + 2 < ktiles) {
            int ns = (kt + 2) % 3;
            loadA(ns, kt + 2);
            loadB(ns, kt + 2);
        }
        cp_commit();

        const uint32_t cA = aS(kt % 3);
        const uint32_t cB = bS(kt % 3);

#pragma unroll
        for (int st = 0; st < 4; st++) {
            const int kkb = st * 32;                  // byte offset of k16 step
            uint32_t af[4][4];
#pragma unroll
            for (int mt = 0; mt < 4; mt++)
                ldsm4(af[mt], cA + SWZ((rm + mt * 16 + a_row) * 128 + kkb + a_ko));
            uint32_t bf[NT][2];
#pragma unroll
            for (int j = 0; j < NT / 2; j++) {
                uint32_t t[4];
                ldsm4(t, cB + SWZ((nb + j * 16 + b_row) * 128 + kkb + b_ko));
                bf[2 * j][0] = t[0]; bf[2 * j][1] = t[1];
                bf[2 * j + 1][0] = t[2]; bf[2 * j + 1][1] = t[3];
            }
#pragma unroll
            for (int mt = 0; mt < 4; mt++)
#pragma unroll
                for (int nt = 0; nt < NT; nt++) mma16816(acc[mt][nt], af[mt], bf[nt]);
        }
        // no trailing barrier: next iteration's top barrier protects stage reuse
    }

    // ---------------- epilogue ----------------
    if (MODE == 0) {
#pragma unroll
        for (int mt = 0; mt < 4; mt++) {
#pragma unroll
            for (int nt = 0; nt < NT; nt++) {
                int row = m0 + wr * 64 + mt * 16 + grp;
                int col = nc0 + wc * WN + nt * 8 + 2 * tig;
                float bb0 = bias[col], bb1 = bias[col + 1];
                float* c = acc[mt][nt];
                store2(C, (size_t)row * Nout + col,       c[0] + bb0, c[1] + bb1);
                store2(C, (size_t)(row + 8) * Nout + col, c[2] + bb0, c[3] + bb1);
            }
        }
    } else if (MODE == 1) {
        const float e2 = alpha * 1.44269504f;      // exp(x*alpha) = exp2(x*alpha*log2e)
#pragma unroll
        for (int mt = 0; mt < 4; mt++) {
            int row = m0 + wr * 64 + mt * 16 + grp;
            float z0 = 0.0f, z1 = 0.0f;
#pragma unroll
            for (int nt = 0; nt < NT; nt++) {
                int col = n0 + wc * WN + nt * 8 + 2 * tig;
                float* c = acc[mt][nt];
                float p0 = exp2f(c[0] * e2), p1 = exp2f(c[1] * e2);
                float p2 = exp2f(c[2] * e2), p3 = exp2f(c[3] * e2);
                store2(C, (size_t)row * Nout + col,       p0, p1);
                store2(C, (size_t)(row + 8) * Nout + col, p2, p3);
                z0 += p0 + p1; z1 += p2 + p3;
            }
            z0 += __shfl_xor_sync(0xffffffffu, z0, 1);
            z0 += __shfl_xor_sync(0xffffffffu, z0, 2);
            z1 += __shfl_xor_sync(0xffffffffu, z1, 1);
            z1 += __shfl_xor_sync(0xffffffffu, z1, 2);
            if (tig == 0) {
                atomicAdd(Z + row,     z0);
                atomicAdd(Z + row + 8, z1);
            }
        }
    } else {   // MODE 2
#pragma unroll
        for (int mt = 0; mt < 4; mt++) {
            int row = m0 + wr * 64 + mt * 16 + grp;
            float iz0 = 1.0f / Z[row];
            float iz8 = 1.0f / Z[row + 8];
#pragma unroll
            for (int nt = 0; nt < NT; nt++) {
                int col = n0 + wc * WN + nt * 8 + 2 * tig;
                float* c = acc[mt][nt];
                store2(C, (size_t)row * Nout + col,       c[0] * iz0, c[1] * iz0);
                store2(C, (size_t)(row + 8) * Nout + col, c[2] * iz8, c[3] * iz8);
            }
        }
    }
}

// ---------------- converts / transposes ----------------
__global__ void f2h_kernel(const float* __restrict__ in, __half* __restrict__ out, size_t n) {
    size_t i = ((size_t)blockIdx.x * blockDim.x + threadIdx.x) * 4;
    if (i < n) {
        float4 v = *(const float4*)(in + i);
        __half2* o = (__half2*)(out + i);
        o[0] = __floats2half2_rn(v.x, v.y);
        o[1] = __floats2half2_rn(v.z, v.w);
    }
}

__global__ void zeroZ_kernel(float* __restrict__ Z) {
    Z[blockIdx.x * 256 + threadIdx.x] = 0.0f;
}

// batched: z selects which W (fp32 [R][C]) -> out + z*R*C (fp16 [C][R])
__global__ void trW_f2h(const float* __restrict__ W0, const float* __restrict__ W1,
                        const float* __restrict__ W2, __half* __restrict__ out,
                        int R, int C) {
    const float* in = (blockIdx.z == 0) ? W0 : (blockIdx.z == 1) ? W1 : W2;
    out += (size_t)blockIdx.z * R * C;
    __shared__ float t[32][33];
    int c0 = blockIdx.x * 32, r0 = blockIdx.y * 32;
#pragma unroll
    for (int i = threadIdx.y; i < 32; i += 8)
        t[i][threadIdx.x] = in[(size_t)(r0 + i) * C + c0 + threadIdx.x];
    __syncthreads();
#pragma unroll
    for (int i = threadIdx.y; i < 32; i += 8)
        out[(size_t)(c0 + i) * R + r0 + threadIdx.x] = __float2half(t[threadIdx.x][i]);
}

__global__ void tr_h(const __half* __restrict__ in, __half* __restrict__ out, int R, int C) {
    in  += (size_t)blockIdx.z * R * C;
    out += (size_t)blockIdx.z * R * C;
    __shared__ __half t[32][33];
    int c0 = blockIdx.x * 32, r0 = blockIdx.y * 32;
#pragma unroll
    for (int i = threadIdx.y; i < 32; i += 8)
        t[i][threadIdx.x] = in[(size_t)(r0 + i) * C + c0 + threadIdx.x];
    __syncthreads();
#pragma unroll
    for (int i = threadIdx.y; i < 32; i += 8)
        out[(size_t)(c0 + i) * R + r0 + threadIdx.x] = t[threadIdx.x][i];
}

// ---------------- launch ----------------
extern "C" void kernel_launch(void* const* d_in, const int* in_sizes, int n_in,
                              void* d_out, int out_size) {
    const float* X  = (const float*)d_in[0];
    const float* Wq = (const float*)d_in[1];
    const float* Wk = (const float*)d_in[2];
    const float* Wv = (const float*)d_in[3];
    const float* bq = (const float*)d_in[4];
    const float* bk = (const float*)d_in[5];
    const float* bv = (const float*)d_in[6];
    float* O = (float*)d_out;

    __half *Xh, *Wt, *Qh, *Kh, *Vh, *Vt, *S;
    float* Zp;
    cudaGetSymbolAddress((void**)&Xh, g_Xh);
    cudaGetSymbolAddress((void**)&Wt, g_Wt);
    cudaGetSymbolAddress((void**)&Qh, g_Qh);
    cudaGetSymbolAddress((void**)&Kh, g_Kh);
    cudaGetSymbolAddress((void**)&Vh, g_Vh);
    cudaGetSymbolAddress((void**)&Vt, g_Vt);
    cudaGetSymbolAddress((void**)&S,  g_S);
    cudaGetSymbolAddress((void**)&Zp, g_Z);

    const int D = 1024, N = 4096;
    const int SMEM_G = 3 * (A_STG + 128 * 128);   // 98304

    static int attr_done = 0;
    if (!attr_done) {
        cudaFuncSetAttribute((const void*)gemm_tn<0, __half>, cudaFuncAttributeMaxDynamicSharedMemorySize, SMEM_G);
        cudaFuncSetAttribute((const void*)gemm_tn<1, __half>, cudaFuncAttributeMaxDynamicSharedMemorySize, SMEM_G);
        cudaFuncSetAttribute((const void*)gemm_tn<2, float>,  cudaFuncAttributeMaxDynamicSharedMemorySize, SMEM_G);
        attr_done = 1;
    }

    // launch index:                                            idx
    {
        size_t n = (size_t)4 * N * D;
        f2h_kernel<<<(unsigned)(n / 4 / 256), 256>>>(X, Xh, n);          // 0
        dim3 b(32, 8), g(D / 32, D / 32, 3);
        trW_f2h<<<g, b>>>(Wq, Wk, Wv, Wt, D, D);                         // 1
        zeroZ_kernel<<<4 * N / 256, 256>>>(Zp);                          // 2
    }

    // 1) fused QKV                                                      // 3
    {
        dim3 g(4 * N / 128, 3 * D / 128, 1);
        gemm_tn<0, __half><<<g, THREADS, SMEM_G>>>(
            Xh, Wt, bq, bk, bv, Qh, Kh, Vh, nullptr, D, D, 0, 0, 0, 1.0f);
    }

    // 2) V transpose per batch                                          // 4
    {
        dim3 b(32, 8), g(D / 32, N / 32, 4);
        tr_h<<<g, b>>>(Vh, Vt, N, D);
    }

    // 3) P = exp(Q K^T / 32), Z row sums                                // 5 (ncu -s5)
    {
        dim3 g(N / 128, N / 128, 4);
        gemm_tn<1, __half><<<g, THREADS, SMEM_G>>>(
            Qh, Kh, nullptr, nullptr, nullptr, S, nullptr, nullptr, Zp,
            N, D, (long long)N * D, (long long)N * D, (long long)N * N, 0.03125f);
    }

    // 4) O = (P Vt^T) / Z                                               // 6
    {
        dim3 g(N / 128, D / 128, 4);
        gemm_tn<2, float><<<g, THREADS, SMEM_G>>>(
            S, Vt, nullptr, nullptr, nullptr, O, nullptr, nullptr, Zp,
            D, N, (long long)N * N, (long long)N * D, (long long)N * D, 1.0f);
    }
}

// round 12
// speedup vs baseline: 4.0944x; 1.0149x over previous
#include <cuda_runtime.h>
#include <cuda_fp16.h>
#include <cstdint>
#include <math.h>

// ---------------------------------------------------------------------------
// SelfAttention B=4, N=4096, d=1024, fp32 in/out, rel_err < 1e-3.
// mma.sync fp16 path, softmax fused into GEMM epilogues.
// GEMMs: BM=128 BN=128, 128 threads (4 warps, 2x2, warp tile 64x64),
// 2 CTAs/SM, BK=64, SW128 smem, cp.async 3-stage, ldmatrix.x4,
// one barrier per k-tile. 4.0 HMMA per ldsm.x4 (was 2.67).
//   0) X -> fp16; Wq/Wk/Wv -> transposed fp16 (one batched launch)
//   1) fused QKV = Xh * Wcat^T + b     (MODE0, fp16 out)
//   2) Vh -> Vt transpose
//   3) P = exp(Q K^T / 32), Z row sums (MODE1, fp16 out)
//   4) O = (P Vt^T) / Z                (MODE2, fp32 out)
// ---------------------------------------------------------------------------

#define THREADS_G 128                 // GEMM CTA threads (4 warps)
#define A_STG 16384                   // 128 rows * 128B

#define SWZ(o) ((o) ^ (((o) >> 3) & 0x70))

// scratch
__device__ __half g_Xh[(size_t)4 * 4096 * 1024];
__device__ __half g_Wt[3ull * 1024 * 1024];        // [3072][1024] (Q,K,V concat)
__device__ __half g_Qh[(size_t)4 * 4096 * 1024];
__device__ __half g_Kh[(size_t)4 * 4096 * 1024];
__device__ __half g_Vh[(size_t)4 * 4096 * 1024];
__device__ __half g_Vt[(size_t)4 * 4096 * 1024];
__device__ __half g_S [(size_t)4 * 4096 * 4096];   // un-normalized exp(S)
__device__ float  g_Z [4 * 4096];                  // row sums of exp(S)

// ---------------- PTX helpers ----------------
__device__ __forceinline__ uint32_t smem_u32(const void* p) {
    uint32_t a;
    asm("{ .reg .u64 t; cvta.to.shared.u64 t, %1; cvt.u32.u64 %0, t; }" : "=r"(a) : "l"(p));
    return a;
}
__device__ __forceinline__ void cp16s(uint32_t s, const void* g) {
    asm volatile("cp.async.cg.shared.global [%0], [%1], 16;\n" :: "r"(s), "l"(g));
}
__device__ __forceinline__ void cp_commit() { asm volatile("cp.async.commit_group;\n"); }
template <int N> __device__ __forceinline__ void cp_wait() {
    asm volatile("cp.async.wait_group %0;\n" :: "n"(N));
}
__device__ __forceinline__ void ldsm4(uint32_t* r, uint32_t addr) {
    asm volatile("ldmatrix.sync.aligned.m8n8.x4.shared.b16 {%0,%1,%2,%3}, [%4];"
        : "=r"(r[0]), "=r"(r[1]), "=r"(r[2]), "=r"(r[3]) : "r"(addr));
}
__device__ __forceinline__ void mma16816(float c[4], const uint32_t a[4], const uint32_t b[2]) {
    asm volatile(
        "mma.sync.aligned.m16n8k16.row.col.f32.f16.f16.f32 "
        "{%0,%1,%2,%3},{%4,%5,%6,%7},{%8,%9},{%0,%1,%2,%3};"
        : "+f"(c[0]), "+f"(c[1]), "+f"(c[2]), "+f"(c[3])
        : "r"(a[0]), "r"(a[1]), "r"(a[2]), "r"(a[3]), "r"(b[0]), "r"(b[1]));
}

__device__ __forceinline__ void store2(__half* C, size_t idx, float v0, float v1) {
    *(__half2*)(C + idx) = __floats2half2_rn(v0, v1);
}
__device__ __forceinline__ void store2(float* C, size_t idx, float v0, float v1) {
    float2 t; t.x = v0; t.y = v1;
    *(float2*)(C + idx) = t;
}

// ---------------- TN GEMM ----------------
// C[m][n] = f( alpha * sum_k A[m][k]*B[n][k] )
// MODE 0: + bias[n], column segments of Nout select C0/C1/C2 (fused QKV)
// MODE 1: exp() in epilogue, row sums atomically added into Z
// MODE 2: multiply by 1/Z[row]
// BM=128, BN=128, 4 warps (2M x 2N), warp tile 64x64, 2 CTAs/SM.
template <int MODE, typename OutT>
__global__ void __launch_bounds__(THREADS_G, 2)
gemm_tn(const __half* __restrict__ A, const __half* __restrict__ B,
        const float* b0p, const float* b1p, const float* b2p,
        OutT* C0, OutT* C1, OutT* C2, float* __restrict__ Z,
        int Nout, int K, long long strA, long long strB, long long strC, float alpha) {
    constexpr int BN_ = 128;
    constexpr int B_STG = BN_ * 128;
    constexpr int OFF_B = 3 * A_STG;
    constexpr int NT = 8;             // 8 n-tiles per warp (64 cols)
    constexpr int WN = 64;            // warp n extent

    extern __shared__ __align__(128) char smem[];
    const uint32_t sb = smem_u32(smem);

    A += (long long)blockIdx.z * strA;
    B += (long long)blockIdx.z * strB;
    if (MODE != 0 && Z) Z += (long long)blockIdx.z * (strC / Nout);

    const int tid  = threadIdx.x;
    const int lane = tid & 31;
    const int warp = tid >> 5;        // 4 warps: 2 (M) x 2 (N)
    const int wr   = warp & 1;
    const int wc   = warp >> 1;
    const int grp  = lane >> 2;
    const int tig  = lane & 3;

    const int m0 = blockIdx.x * 128;   // m on x: consecutive CTAs share B tile
    const int n0 = blockIdx.y * BN_;

    const int seg = (MODE == 0) ? (n0 / Nout) : 0;
    const int nc0 = n0 - seg * Nout;
    OutT* C = (seg == 0) ? C0 : (seg == 1) ? C1 : C2;
    const float* bias = (seg == 0) ? b0p : (seg == 1) ? b1p : b2p;
    C += (long long)blockIdx.z * strC;

    float acc[4][NT][4];
#pragma unroll
    for (int i = 0; i < 4; i++)
#pragma unroll
        for (int j = 0; j < NT; j++)
#pragma unroll
            for (int v = 0; v < 4; v++) acc[i][j][v] = 0.0f;

    auto aS = [&](int s) -> uint32_t { return sb + s * A_STG; };
    auto bS = [&](int s) -> uint32_t { return sb + OFF_B + s * B_STG; };

    auto loadA = [&](int s, int kt) {
#pragma unroll
        for (int i = 0; i < 8; i++) {
            int c = i * THREADS_G + tid;      // 1024 16B chunks
            int row = c >> 3, ch = c & 7;
            cp16s(aS(s) + SWZ(row * 128 + ch * 16),
                  A + (size_t)(m0 + row) * K + kt * 64 + ch * 8);
        }
    };
    auto loadB = [&](int s, int kt) {
#pragma unroll
        for (int i = 0; i < 8; i++) {         // 1024 16B chunks
            int c = i * THREADS_G + tid;
            int row = c >> 3, ch = c & 7;
            cp16s(bS(s) + SWZ(row * 128 + ch * 16),
                  B + (size_t)(n0 + row) * K + kt * 64 + ch * 8);
        }
    };

    const int ktiles = K / 64;
    loadA(0, 0); loadB(0, 0); cp_commit();
    loadA(1, 1); loadB(1, 1); cp_commit();

    // per-thread ldmatrix lane offsets
    const int a_row = lane & 15;                      // row within 16
    const int a_ko  = (lane >> 4) << 4;               // 0 / 16 bytes
    const int b_row = (lane & 7) + ((lane >> 4) << 3);// row within 16
    const int b_ko  = ((lane >> 3) & 1) << 4;         // 0 / 16 bytes
    const int rm = wr * 64;
    const int nb = wc * WN;

    for (int kt = 0; kt < ktiles; kt++) {
        cp_wait<1>();
        __syncthreads();   // single barrier: orders stage reuse AND data ready

        if (kt + 2 < ktiles) {
            int ns = (kt + 2) % 3;
            loadA(ns, kt + 2);
            loadB(ns, kt + 2);
        }
        cp_commit();

        const uint32_t cA = aS(kt % 3);
        const uint32_t cB = bS(kt % 3);

#pragma unroll
        for (int st = 0; st < 4; st++) {
            const int kkb = st * 32;                  // byte offset of k16 step
            uint32_t af[4][4];
#pragma unroll
            for (int mt = 0; mt < 4; mt++)
                ldsm4(af[mt], cA + SWZ((rm + mt * 16 + a_row) * 128 + kkb + a_ko));
            uint32_t bf[NT][2];
#pragma unroll
            for (int j = 0; j < NT / 2; j++) {
                uint32_t t[4];
                ldsm4(t, cB + SWZ((nb + j * 16 + b_row) * 128 + kkb + b_ko));
                bf[2 * j][0] = t[0]; bf[2 * j][1] = t[1];
                bf[2 * j + 1][0] = t[2]; bf[2 * j + 1][1] = t[3];
            }
#pragma unroll
            for (int mt = 0; mt < 4; mt++)
#pragma unroll
                for (int nt = 0; nt < NT; nt++) mma16816(acc[mt][nt], af[mt], bf[nt]);
        }
        // no trailing barrier: next iteration's top barrier protects stage reuse
    }

    // ---------------- epilogue ----------------
    if (MODE == 0) {
#pragma unroll
        for (int mt = 0; mt < 4; mt++) {
#pragma unroll
            for (int nt = 0; nt < NT; nt++) {
                int row = m0 + wr * 64 + mt * 16 + grp;
                int col = nc0 + wc * WN + nt * 8 + 2 * tig;
                float bb0 = bias[col], bb1 = bias[col + 1];
                float* c = acc[mt][nt];
                store2(C, (size_t)row * Nout + col,       c[0] + bb0, c[1] + bb1);
                store2(C, (size_t)(row + 8) * Nout + col, c[2] + bb0, c[3] + bb1);
            }
        }
    } else if (MODE == 1) {
        const float e2 = alpha * 1.44269504f;      // exp(x*alpha) = exp2(x*alpha*log2e)
#pragma unroll
        for (int mt = 0; mt < 4; mt++) {
            int row = m0 + wr * 64 + mt * 16 + grp;
            float z0 = 0.0f, z1 = 0.0f;
#pragma unroll
            for (int nt = 0; nt < NT; nt++) {
                int col = n0 + wc * WN + nt * 8 + 2 * tig;
                float* c = acc[mt][nt];
                float p0 = exp2f(c[0] * e2), p1 = exp2f(c[1] * e2);
                float p2 = exp2f(c[2] * e2), p3 = exp2f(c[3] * e2);
                store2(C, (size_t)row * Nout + col,       p0, p1);
                store2(C, (size_t)(row + 8) * Nout + col, p2, p3);
                z0 += p0 + p1; z1 += p2 + p3;
            }
            z0 += __shfl_xor_sync(0xffffffffu, z0, 1);
            z0 += __shfl_xor_sync(0xffffffffu, z0, 2);
            z1 += __shfl_xor_sync(0xffffffffu, z1, 1);
            z1 += __shfl_xor_sync(0xffffffffu, z1, 2);
            if (tig == 0) {
                atomicAdd(Z + row,     z0);
                atomicAdd(Z + row + 8, z1);
            }
        }
    } else {   // MODE 2
#pragma unroll
        for (int mt = 0; mt < 4; mt++) {
            int row = m0 + wr * 64 + mt * 16 + grp;
            float iz0 = 1.0f / Z[row];
            float iz8 = 1.0f / Z[row + 8];
#pragma unroll
            for (int nt = 0; nt < NT; nt++) {
                int col = n0 + wc * WN + nt * 8 + 2 * tig;
                float* c = acc[mt][nt];
                store2(C, (size_t)row * Nout + col,       c[0] * iz0, c[1] * iz0);
                store2(C, (size_t)(row + 8) * Nout + col, c[2] * iz8, c[3] * iz8);
            }
        }
    }
}

// ---------------- converts / transposes ----------------
__global__ void f2h_kernel(const float* __restrict__ in, __half* __restrict__ out, size_t n) {
    size_t i = ((size_t)blockIdx.x * blockDim.x + threadIdx.x) * 4;
    if (i < n) {
        float4 v = *(const float4*)(in + i);
        __half2* o = (__half2*)(out + i);
        o[0] = __floats2half2_rn(v.x, v.y);
        o[1] = __floats2half2_rn(v.z, v.w);
    }
}

__global__ void zeroZ_kernel(float* __restrict__ Z) {
    Z[blockIdx.x * 256 + threadIdx.x] = 0.0f;
}

// batched: z selects which W (fp32 [R][C]) -> out + z*R*C (fp16 [C][R])
__global__ void trW_f2h(const float* __restrict__ W0, const float* __restrict__ W1,
                        const float* __restrict__ W2, __half* __restrict__ out,
                        int R, int C) {
    const float* in = (blockIdx.z == 0) ? W0 : (blockIdx.z == 1) ? W1 : W2;
    out += (size_t)blockIdx.z * R * C;
    __shared__ float t[32][33];
    int c0 = blockIdx.x * 32, r0 = blockIdx.y * 32;
#pragma unroll
    for (int i = threadIdx.y; i < 32; i += 8)
        t[i][threadIdx.x] = in[(size_t)(r0 + i) * C + c0 + threadIdx.x];
    __syncthreads();
#pragma unroll
    for (int i = threadIdx.y; i < 32; i += 8)
        out[(size_t)(c0 + i) * R + r0 + threadIdx.x] = __float2half(t[threadIdx.x][i]);
}

__global__ void tr_h(const __half* __restrict__ in, __half* __restrict__ out, int R, int C) {
    in  += (size_t)blockIdx.z * R * C;
    out += (size_t)blockIdx.z * R * C;
    __shared__ __half t[32][33];
    int c0 = blockIdx.x * 32, r0 = blockIdx.y * 32;
#pragma unroll
    for (int i = threadIdx.y; i < 32; i += 8)
        t[i][threadIdx.x] = in[(size_t)(r0 + i) * C + c0 + threadIdx.x];
    __syncthreads();
#pragma unroll
    for (int i = threadIdx.y; i < 32; i += 8)
        out[(size_t)(c0 + i) * R + r0 + threadIdx.x] = t[threadIdx.x][i];
}

// ---------------- launch ----------------
extern "C" void kernel_launch(void* const* d_in, const int* in_sizes, int n_in,
                              void* d_out, int out_size) {
    const float* X  = (const float*)d_in[0];
    const float* Wq = (const float*)d_in[1];
    const float* Wk = (const float*)d_in[2];
    const float* Wv = (const float*)d_in[3];
    const float* bq = (const float*)d_in[4];
    const float* bk = (const float*)d_in[5];
    const float* bv = (const float*)d_in[6];
    float* O = (float*)d_out;

    __half *Xh, *Wt, *Qh, *Kh, *Vh, *Vt, *S;
    float* Zp;
    cudaGetSymbolAddress((void**)&Xh, g_Xh);
    cudaGetSymbolAddress((void**)&Wt, g_Wt);
    cudaGetSymbolAddress((void**)&Qh, g_Qh);
    cudaGetSymbolAddress((void**)&Kh, g_Kh);
    cudaGetSymbolAddress((void**)&Vh, g_Vh);
    cudaGetSymbolAddress((void**)&Vt, g_Vt);
    cudaGetSymbolAddress((void**)&S,  g_S);
    cudaGetSymbolAddress((void**)&Zp, g_Z);

    const int D = 1024, N = 4096;
    const int SMEM_G = 3 * (A_STG + 128 * 128);   // 98304

    static int attr_done = 0;
    if (!attr_done) {
        cudaFuncSetAttribute((const void*)gemm_tn<0, __half>, cudaFuncAttributeMaxDynamicSharedMemorySize, SMEM_G);
        cudaFuncSetAttribute((const void*)gemm_tn<1, __half>, cudaFuncAttributeMaxDynamicSharedMemorySize, SMEM_G);
        cudaFuncSetAttribute((const void*)gemm_tn<2, float>,  cudaFuncAttributeMaxDynamicSharedMemorySize, SMEM_G);
        attr_done = 1;
    }

    // launch index:                                            idx
    {
        size_t n = (size_t)4 * N * D;
        f2h_kernel<<<(unsigned)(n / 4 / 256), 256>>>(X, Xh, n);          // 0
        dim3 b(32, 8), g(D / 32, D / 32, 3);
        trW_f2h<<<g, b>>>(Wq, Wk, Wv, Wt, D, D);                         // 1
        zeroZ_kernel<<<4 * N / 256, 256>>>(Zp);                          // 2
    }

    // 1) fused QKV                                                      // 3
    {
        dim3 g(4 * N / 128, 3 * D / 128, 1);
        gemm_tn<0, __half><<<g, THREADS_G, SMEM_G>>>(
            Xh, Wt, bq, bk, bv, Qh, Kh, Vh, nullptr, D, D, 0, 0, 0, 1.0f);
    }

    // 2) V transpose per batch                                          // 4
    {
        dim3 b(32, 8), g(D / 32, N / 32, 4);
        tr_h<<<g, b>>>(Vh, Vt, N, D);
    }

    // 3) P = exp(Q K^T / 32), Z row sums                                // 5 (ncu -s5)
    {
        dim3 g(N / 128, N / 128, 4);
        gemm_tn<1, __half><<<g, THREADS_G, SMEM_G>>>(
            Qh, Kh, nullptr, nullptr, nullptr, S, nullptr, nullptr, Zp,
            N, D, (long long)N * D, (long long)N * D, (long long)N * N, 0.03125f);
    }

    // 4) O = (P Vt^T) / Z                                               // 6
    {
        dim3 g(N / 128, D / 128, 4);
        gemm_tn<2, float><<<g, THREADS_G, SMEM_G>>>(
            S, Vt, nullptr, nullptr, nullptr, O, nullptr, nullptr, Zp,
            D, N, (long long)N * N, (long long)N * D, (long long)N * D, 1.0f);
    }
}

// round 17
// speedup vs baseline: 4.2658x; 1.0419x over previous
#include <cuda_runtime.h>
#include <cuda_fp16.h>
#include <cstdint>
#include <math.h>

// ---------------------------------------------------------------------------
// SelfAttention B=4, N=4096, d=1024, fp32 in/out, rel_err < 1e-3.
// mma.sync fp16 path, softmax fused into GEMM epilogues.
// GEMMs: BM=128 BN=128, 128 threads (4 warps, 2x2, warp tile 64x64),
// 2 CTAs/SM, BK=64, SW128 smem, cp.async 3-stage, ldmatrix.x4,
// one barrier per k-tile.
// V transpose FUSED into the QKV epilogue: seg==2 CTAs stage their tile in
// smem and write Vt [e][n] directly with coalesced stores (tr_h removed).
//   0) X -> fp16; Wq/Wk/Wv -> transposed fp16 (one batched launch)
//   1) fused QKV = Xh * Wcat^T + b     (MODE0, fp16; V written transposed)
//   2) P = exp(Q K^T / 32), Z row sums (MODE1, fp16 out)
//   3) O = (P Vt^T) / Z                (MODE2, fp32 out)
// ---------------------------------------------------------------------------

#define THREADS_G 128                 // GEMM CTA threads (4 warps)
#define A_STG 16384                   // 128 rows * 128B

#define SWZ(o) ((o) ^ (((o) >> 3) & 0x70))

// scratch
__device__ __half g_Xh[(size_t)4 * 4096 * 1024];
__device__ __half g_Wt[3ull * 1024 * 1024];        // [3072][1024] (Q,K,V concat)
__device__ __half g_Qh[(size_t)4 * 4096 * 1024];
__device__ __half g_Kh[(size_t)4 * 4096 * 1024];
__device__ __half g_Vt[(size_t)4 * 4096 * 1024];   // [b][e][n]
__device__ __half g_S [(size_t)4 * 4096 * 4096];   // un-normalized exp(S)
__device__ float  g_Z [4 * 4096];                  // row sums of exp(S)

// ---------------- PTX helpers ----------------
__device__ __forceinline__ uint32_t smem_u32(const void* p) {
    uint32_t a;
    asm("{ .reg .u64 t; cvta.to.shared.u64 t, %1; cvt.u32.u64 %0, t; }" : "=r"(a) : "l"(p));
    return a;
}
__device__ __forceinline__ void cp16s(uint32_t s, const void* g) {
    asm volatile("cp.async.cg.shared.global [%0], [%1], 16;\n" :: "r"(s), "l"(g));
}
__device__ __forceinline__ void cp_commit() { asm volatile("cp.async.commit_group;\n"); }
template <int N> __device__ __forceinline__ void cp_wait() {
    asm volatile("cp.async.wait_group %0;\n" :: "n"(N));
}
__device__ __forceinline__ void ldsm4(uint32_t* r, uint32_t addr) {
    asm volatile("ldmatrix.sync.aligned.m8n8.x4.shared.b16 {%0,%1,%2,%3}, [%4];"
        : "=r"(r[0]), "=r"(r[1]), "=r"(r[2]), "=r"(r[3]) : "r"(addr));
}
__device__ __forceinline__ void mma16816(float c[4], const uint32_t a[4], const uint32_t b[2]) {
    asm volatile(
        "mma.sync.aligned.m16n8k16.row.col.f32.f16.f16.f32 "
        "{%0,%1,%2,%3},{%4,%5,%6,%7},{%8,%9},{%0,%1,%2,%3};"
        : "+f"(c[0]), "+f"(c[1]), "+f"(c[2]), "+f"(c[3])
        : "r"(a[0]), "r"(a[1]), "r"(a[2]), "r"(a[3]), "r"(b[0]), "r"(b[1]));
}

__device__ __forceinline__ void store2(__half* C, size_t idx, float v0, float v1) {
    *(__half2*)(C + idx) = __floats2half2_rn(v0, v1);
}
__device__ __forceinline__ void store2(float* C, size_t idx, float v0, float v1) {
    float2 t; t.x = v0; t.y = v1;
    *(float2*)(C + idx) = t;
}

// ---------------- TN GEMM ----------------
// C[m][n] = f( alpha * sum_k A[m][k]*B[n][k] )
// MODE 0: + bias[n]; column segments select Q / K / V-transposed outputs
// MODE 1: exp() in epilogue, row sums atomically added into Z
// MODE 2: multiply by 1/Z[row]
// BM=128, BN=128, 4 warps (2M x 2N), warp tile 64x64, 2 CTAs/SM.
template <int MODE, typename OutT>
__global__ void __launch_bounds__(THREADS_G, 2)
gemm_tn(const __half* __restrict__ A, const __half* __restrict__ B,
        const float* b0p, const float* b1p, const float* b2p,
        OutT* C0, OutT* C1, OutT* C2, float* __restrict__ Z,
        int Nout, int K, long long strA, long long strB, long long strC, float alpha) {
    constexpr int BN_ = 128;
    constexpr int B_STG = BN_ * 128;
    constexpr int OFF_B = 3 * A_STG;
    constexpr int NT = 8;             // 8 n-tiles per warp (64 cols)
    constexpr int WN = 64;            // warp n extent

    extern __shared__ __align__(128) char smem[];
    const uint32_t sb = smem_u32(smem);

    A += (long long)blockIdx.z * strA;
    B += (long long)blockIdx.z * strB;
    if (MODE != 0 && Z) Z += (long long)blockIdx.z * (strC / Nout);

    const int tid  = threadIdx.x;
    const int lane = tid & 31;
    const int warp = tid >> 5;        // 4 warps: 2 (M) x 2 (N)
    const int wr   = warp & 1;
    const int wc   = warp >> 1;
    const int grp  = lane >> 2;
    const int tig  = lane & 3;

    const int m0 = blockIdx.x * 128;   // m on x: consecutive CTAs share B tile
    const int n0 = blockIdx.y * BN_;

    const int seg = (MODE == 0) ? (n0 / Nout) : 0;
    const int nc0 = n0 - seg * Nout;
    OutT* C = (seg == 0) ? C0 : (seg == 1) ? C1 : C2;
    const float* bias = (seg == 0) ? b0p : (seg == 1) ? b1p : b2p;
    C += (long long)blockIdx.z * strC;

    float acc[4][NT][4];
#pragma unroll
    for (int i = 0; i < 4; i++)
#pragma unroll
        for (int j = 0; j < NT; j++)
#pragma unroll
            for (int v = 0; v < 4; v++) acc[i][j][v] = 0.0f;

    auto aS = [&](int s) -> uint32_t { return sb + s * A_STG; };
    auto bS = [&](int s) -> uint32_t { return sb + OFF_B + s * B_STG; };

    auto loadA = [&](int s, int kt) {
#pragma unroll
        for (int i = 0; i < 8; i++) {
            int c = i * THREADS_G + tid;      // 1024 16B chunks
            int row = c >> 3, ch = c & 7;
            cp16s(aS(s) + SWZ(row * 128 + ch * 16),
                  A + (size_t)(m0 + row) * K + kt * 64 + ch * 8);
        }
    };
    auto loadB = [&](int s, int kt) {
#pragma unroll
        for (int i = 0; i < 8; i++) {         // 1024 16B chunks
            int c = i * THREADS_G + tid;
            int row = c >> 3, ch = c & 7;
            cp16s(bS(s) + SWZ(row * 128 + ch * 16),
                  B + (size_t)(n0 + row) * K + kt * 64 + ch * 8);
        }
    };

    const int ktiles = K / 64;
    loadA(0, 0); loadB(0, 0); cp_commit();
    loadA(1, 1); loadB(1, 1); cp_commit();

    // per-thread ldmatrix lane offsets
    const int a_row = lane & 15;                      // row within 16
    const int a_ko  = (lane >> 4) << 4;               // 0 / 16 bytes
    const int b_row = (lane & 7) + ((lane >> 4) << 3);// row within 16
    const int b_ko  = ((lane >> 3) & 1) << 4;         // 0 / 16 bytes
    const int rm = wr * 64;
    const int nb = wc * WN;

    for (int kt = 0; kt < ktiles; kt++) {
        cp_wait<1>();
        __syncthreads();   // single barrier: orders stage reuse AND data ready

        if (kt + 2 < ktiles) {
            int ns = (kt + 2) % 3;
            loadA(ns, kt + 2);
            loadB(ns, kt + 2);
        }
        cp_commit();

        const uint32_t cA = aS(kt % 3);
        const uint32_t cB = bS(kt % 3);

#pragma unroll
        for (int st = 0; st < 4; st++) {
            const int kkb = st * 32;                  // byte offset of k16 step
            uint32_t af[4][4];
#pragma unroll
            for (int mt = 0; mt < 4; mt++)
                ldsm4(af[mt], cA + SWZ((rm + mt * 16 + a_row) * 128 + kkb + a_ko));
            uint32_t bf[NT][2];
#pragma unroll
            for (int j = 0; j < NT / 2; j++) {
                uint32_t t[4];
                ldsm4(t, cB + SWZ((nb + j * 16 + b_row) * 128 + kkb + b_ko));
                bf[2 * j][0] = t[0]; bf[2 * j][1] = t[1];
                bf[2 * j + 1][0] = t[2]; bf[2 * j + 1][1] = t[3];
            }
#pragma unroll
            for (int mt = 0; mt < 4; mt++)
#pragma unroll
                for (int nt = 0; nt < NT; nt++) mma16816(acc[mt][nt], af[mt], bf[nt]);
        }
        // no trailing barrier: next iteration's top barrier protects stage reuse
    }

    // ---------------- epilogue ----------------
    if (MODE == 0) {
        if (seg < 2) {
            // Q / K: plain row-major store + bias
#pragma unroll
            for (int mt = 0; mt < 4; mt++) {
#pragma unroll
                for (int nt = 0; nt < NT; nt++) {
                    int row = m0 + wr * 64 + mt * 16 + grp;
                    int col = nc0 + wc * WN + nt * 8 + 2 * tig;
                    float bb0 = bias[col], bb1 = bias[col + 1];
                    float* c = acc[mt][nt];
                    store2(C, (size_t)row * Nout + col,       c[0] + bb0, c[1] + bb1);
                    store2(C, (size_t)(row + 8) * Nout + col, c[2] + bb0, c[3] + bb1);
                }
            }
        } else {
            // V: stage transposed in smem, write Vt[b][e][n] coalesced.
            __half* stg = (__half*)smem;          // [128 cols][136 rows pad]
            __syncthreads();                       // mainloop smem reads done
#pragma unroll
            for (int mt = 0; mt < 4; mt++) {
#pragma unroll
                for (int nt = 0; nt < NT; nt++) {
                    int row = wr * 64 + mt * 16 + grp;        // local token
                    int col = wc * WN + nt * 8 + 2 * tig;     // local e
                    float bb0 = bias[nc0 + col], bb1 = bias[nc0 + col + 1];
                    float* c = acc[mt][nt];
                    stg[(col)     * 136 + row]     = __float2half(c[0] + bb0);
                    stg[(col + 1) * 136 + row]     = __float2half(c[1] + bb1);
                    stg[(col)     * 136 + row + 8] = __float2half(c[2] + bb0);
                    stg[(col + 1) * 136 + row + 8] = __float2half(c[3] + bb1);
                }
            }
            __syncthreads();
            const int bb   = m0 >> 12;            // batch = m0 / 4096
            const int nloc = m0 & 4095;           // token offset within batch
            const int tr   = tid >> 3;            // 0..15
            const int toff = (tid & 7) * 16;      // halves (32B)
#pragma unroll
            for (int p = 0; p < 8; p++) {
                int col = p * 16 + tr;            // local e, 0..127
                int e = nc0 + col;
                const uint4* src = (const uint4*)(stg + (size_t)col * 136 + toff);
                uint4 v0 = src[0], v1 = src[1];   // 16 halves
                uint4* dst = (uint4*)((__half*)C +
                    ((size_t)bb * 1024 + e) * 4096 + nloc + toff);
                dst[0] = v0; dst[1] = v1;
            }
        }
    } else if (MODE == 1) {
        const float e2 = alpha * 1.44269504f;      // exp(x*alpha) = exp2(x*alpha*log2e)
#pragma unroll
        for (int mt = 0; mt < 4; mt++) {
            int row = m0 + wr * 64 + mt * 16 + grp;
            float z0 = 0.0f, z1 = 0.0f;
#pragma unroll
            for (int nt = 0; nt < NT; nt++) {
                int col = n0 + wc * WN + nt * 8 + 2 * tig;
                float* c = acc[mt][nt];
                float p0 = exp2f(c[0] * e2), p1 = exp2f(c[1] * e2);
                float p2 = exp2f(c[2] * e2), p3 = exp2f(c[3] * e2);
                store2(C, (size_t)row * Nout + col,       p0, p1);
                store2(C, (size_t)(row + 8) * Nout + col, p2, p3);
                z0 += p0 + p1; z1 += p2 + p3;
            }
            z0 += __shfl_xor_sync(0xffffffffu, z0, 1);
            z0 += __shfl_xor_sync(0xffffffffu, z0, 2);
            z1 += __shfl_xor_sync(0xffffffffu, z1, 1);
            z1 += __shfl_xor_sync(0xffffffffu, z1, 2);
            if (tig == 0) {
                atomicAdd(Z + row,     z0);
                atomicAdd(Z + row + 8, z1);
            }
        }
    } else {   // MODE 2
#pragma unroll
        for (int mt = 0; mt < 4; mt++) {
            int row = m0 + wr * 64 + mt * 16 + grp;
            float iz0 = 1.0f / Z[row];
            float iz8 = 1.0f / Z[row + 8];
#pragma unroll
            for (int nt = 0; nt < NT; nt++) {
                int col = n0 + wc * WN + nt * 8 + 2 * tig;
                float* c = acc[mt][nt];
                store2(C, (size_t)row * Nout + col,       c[0] * iz0, c[1] * iz0);
                store2(C, (size_t)(row + 8) * Nout + col, c[2] * iz8, c[3] * iz8);
            }
        }
    }
}

// ---------------- converts ----------------
__global__ void f2h_kernel(const float* __restrict__ in, __half* __restrict__ out, size_t n) {
    size_t i = ((size_t)blockIdx.x * blockDim.x + threadIdx.x) * 4;
    if (i < n) {
        float4 v = *(const float4*)(in + i);
        __half2* o = (__half2*)(out + i);
        o[0] = __floats2half2_rn(v.x, v.y);
        o[1] = __floats2half2_rn(v.z, v.w);
    }
}

__global__ void zeroZ_kernel(float* __restrict__ Z) {
    Z[blockIdx.x * 256 + threadIdx.x] = 0.0f;
}

// batched: z selects which W (fp32 [R][C]) -> out + z*R*C (fp16 [C][R])
__global__ void trW_f2h(const float* __restrict__ W0, const float* __restrict__ W1,
                        const float* __restrict__ W2, __half* __restrict__ out,
                        int R, int C) {
    const float* in = (blockIdx.z == 0) ? W0 : (blockIdx.z == 1) ? W1 : W2;
    out += (size_t)blockIdx.z * R * C;
    __shared__ float t[32][33];
    int c0 = blockIdx.x * 32, r0 = blockIdx.y * 32;
#pragma unroll
    for (int i = threadIdx.y; i < 32; i += 8)
        t[i][threadIdx.x] = in[(size_t)(r0 + i) * C + c0 + threadIdx.x];
    __syncthreads();
#pragma unroll
    for (int i = threadIdx.y; i < 32; i += 8)
        out[(size_t)(c0 + i) * R + r0 + threadIdx.x] = __float2half(t[threadIdx.x][i]);
}

// ---------------- launch ----------------
extern "C" void kernel_launch(void* const* d_in, const int* in_sizes, int n_in,
                              void* d_out, int out_size) {
    const float* X  = (const float*)d_in[0];
    const float* Wq = (const float*)d_in[1];
    const float* Wk = (const float*)d_in[2];
    const float* Wv = (const float*)d_in[3];
    const float* bq = (const float*)d_in[4];
    const float* bk = (const float*)d_in[5];
    const float* bv = (const float*)d_in[6];
    float* O = (float*)d_out;

    __half *Xh, *Wt, *Qh, *Kh, *Vt, *S;
    float* Zp;
    cudaGetSymbolAddress((void**)&Xh, g_Xh);
    cudaGetSymbolAddress((void**)&Wt, g_Wt);
    cudaGetSymbolAddress((void**)&Qh, g_Qh);
    cudaGetSymbolAddress((void**)&Kh, g_Kh);
    cudaGetSymbolAddress((void**)&Vt, g_Vt);
    cudaGetSymbolAddress((void**)&S,  g_S);
    cudaGetSymbolAddress((void**)&Zp, g_Z);

    const int D = 1024, N = 4096;
    const int SMEM_G = 3 * (A_STG + 128 * 128);   // 98304

    static int attr_done = 0;
    if (!attr_done) {
        cudaFuncSetAttribute((const void*)gemm_tn<0, __half>, cudaFuncAttributeMaxDynamicSharedMemorySize, SMEM_G);
        cudaFuncSetAttribute((const void*)gemm_tn<1, __half>, cudaFuncAttributeMaxDynamicSharedMemorySize, SMEM_G);
        cudaFuncSetAttribute((const void*)gemm_tn<2, float>,  cudaFuncAttributeMaxDynamicSharedMemorySize, SMEM_G);
        attr_done = 1;
    }

    // launch index:                                            idx
    {
        size_t n = (size_t)4 * N * D;
        f2h_kernel<<<(unsigned)(n / 4 / 256), 256>>>(X, Xh, n);          // 0
        dim3 b(32, 8), g(D / 32, D / 32, 3);
        trW_f2h<<<g, b>>>(Wq, Wk, Wv, Wt, D, D);                         // 1
        zeroZ_kernel<<<4 * N / 256, 256>>>(Zp);                          // 2
    }

    // 1) fused QKV; V written transposed into Vt                        // 3
    {
        dim3 g(4 * N / 128, 3 * D / 128, 1);
        gemm_tn<0, __half><<<g, THREADS_G, SMEM_G>>>(
            Xh, Wt, bq, bk, bv, Qh, Kh, Vt, nullptr, D, D, 0, 0, 0, 1.0f);
    }

    // 2) P = exp(Q K^T / 32), Z row sums                                // 4
    {
        dim3 g(N / 128, N / 128, 4);
        gemm_tn<1, __half><<<g, THREADS_G, SMEM_G>>>(
            Qh, Kh, nullptr, nullptr, nullptr, S, nullptr, nullptr, Zp,
            N, D, (long long)N * D, (long long)N * D, (long long)N * N, 0.03125f);
    }

    // 3) O = (P Vt^T) / Z                                               // 5 (ncu -s5)
    {
        dim3 g(N / 128, D / 128, 4);
        gemm_tn<2, float><<<g, THREADS_G, SMEM_G>>>(
            S, Vt, nullptr, nullptr, nullptr, O, nullptr, nullptr, Zp,
            D, N, (long long)N * N, (long long)N * D, (long long)N * D, 1.0f);
    }
}